// round 1
// baseline (speedup 1.0000x reference)
#include <cuda_runtime.h>
#include <cfloat>
#include <cmath>

#define BN 64
#define SS 1024
#define EE 512
#define KK 1024   // 2*E
#define NN 1024   // 2*E
#define SM1 1023  // S-1
#define AA 128

// scratch: position scores (B x S, only first S-1 used per row)
__device__ float g_scores[BN * SS];

// ---------------------------------------------------------------------------
// Kernel A: fused scores = relu(X @ W1p + b1p) @ w2p
// X row (b,s) = 1024 contiguous floats at states[b, s, 0]
// grid: (16 s-tiles, 64 batches), 256 threads, 64x64 tile, K-tile 32
// ---------------------------------------------------------------------------
__global__ __launch_bounds__(256) void pos_scores_kernel(
    const float* __restrict__ states, const float* __restrict__ W1p,
    const float* __restrict__ b1p, const float* __restrict__ w2p)
{
    const int s0  = blockIdx.x * 64;
    const int b   = blockIdx.y;
    const int tid = threadIdx.x;
    const int tx  = tid & 15;
    const int ty  = tid >> 4;
    const int tx4 = tx * 4;
    const int ty4 = ty * 4;

    __shared__ float As[64][36];   // [m][k], row stride 144B (16B aligned)
    __shared__ float Bs[32][68];   // [k][f], row stride 272B (16B aligned)
    __shared__ float red[64][17];

    const float* Ab = states + (size_t)b * SS * EE;

    float ps[4] = {0.f, 0.f, 0.f, 0.f};

    const int a_ml = tid >> 3;          // 0..31
    const int a_kk = (tid & 7) * 4;     // 0..28
    const int b_kr = tid >> 4;          // 0..15
    const int b_fv = (tid & 15) * 4;    // 0..60

    for (int ntile = 0; ntile < 16; ++ntile) {
        const int f0 = ntile * 64;
        float acc[4][4] = {};

        for (int k0 = 0; k0 < KK; k0 += 32) {
            // load A tile 64x32 (clamp row so s=1023 stays in-bounds)
            #pragma unroll
            for (int it = 0; it < 2; ++it) {
                int m = a_ml + it * 32;
                int srow = s0 + m;
                if (srow > SS - 2) srow = SS - 2;
                float4 v = *(const float4*)(Ab + (size_t)srow * EE + (k0 + a_kk));
                *(float4*)&As[m][a_kk] = v;
            }
            // load B tile 32x64
            #pragma unroll
            for (int it = 0; it < 2; ++it) {
                int kr = b_kr + it * 16;
                float4 v = *(const float4*)(W1p + (size_t)(k0 + kr) * NN + f0 + b_fv);
                *(float4*)&Bs[kr][b_fv] = v;
            }
            __syncthreads();

            #pragma unroll
            for (int k = 0; k < 32; ++k) {
                float a0 = As[ty4 + 0][k];
                float a1 = As[ty4 + 1][k];
                float a2 = As[ty4 + 2][k];
                float a3 = As[ty4 + 3][k];
                float4 bv = *(const float4*)&Bs[k][tx4];
                acc[0][0] = fmaf(a0, bv.x, acc[0][0]);
                acc[0][1] = fmaf(a0, bv.y, acc[0][1]);
                acc[0][2] = fmaf(a0, bv.z, acc[0][2]);
                acc[0][3] = fmaf(a0, bv.w, acc[0][3]);
                acc[1][0] = fmaf(a1, bv.x, acc[1][0]);
                acc[1][1] = fmaf(a1, bv.y, acc[1][1]);
                acc[1][2] = fmaf(a1, bv.z, acc[1][2]);
                acc[1][3] = fmaf(a1, bv.w, acc[1][3]);
                acc[2][0] = fmaf(a2, bv.x, acc[2][0]);
                acc[2][1] = fmaf(a2, bv.y, acc[2][1]);
                acc[2][2] = fmaf(a2, bv.z, acc[2][2]);
                acc[2][3] = fmaf(a2, bv.w, acc[2][3]);
                acc[3][0] = fmaf(a3, bv.x, acc[3][0]);
                acc[3][1] = fmaf(a3, bv.y, acc[3][1]);
                acc[3][2] = fmaf(a3, bv.z, acc[3][2]);
                acc[3][3] = fmaf(a3, bv.w, acc[3][3]);
            }
            __syncthreads();
        }

        // fused epilogue: relu(pre + b1p) . w2p  (b2p dropped: softmax-invariant)
        float4 bias = *(const float4*)(b1p + f0 + tx4);
        float4 wv   = *(const float4*)(w2p + f0 + tx4);
        #pragma unroll
        for (int r = 0; r < 4; ++r) {
            ps[r] += fmaxf(acc[r][0] + bias.x, 0.f) * wv.x
                   + fmaxf(acc[r][1] + bias.y, 0.f) * wv.y
                   + fmaxf(acc[r][2] + bias.z, 0.f) * wv.z
                   + fmaxf(acc[r][3] + bias.w, 0.f) * wv.w;
        }
    }

    // reduce ps over the 16 tx lanes sharing each row (deterministic order)
    #pragma unroll
    for (int r = 0; r < 4; ++r) red[ty4 + r][tx] = ps[r];
    __syncthreads();
    if (tid < 64) {
        float s = 0.f;
        #pragma unroll
        for (int j = 0; j < 16; ++j) s += red[tid][j];
        int srow = s0 + tid;
        if (srow < SM1) g_scores[b * SS + srow] = s;
    }
}

// ---------------------------------------------------------------------------
// Kernel B: masked log-softmax over positions -> logp_pos (row 0), ent_pos (row 3)
// ---------------------------------------------------------------------------
__global__ __launch_bounds__(256) void pos_softmax_kernel(
    const int* __restrict__ lengths, const int* __restrict__ pos_action,
    float* __restrict__ out)
{
    const int b = blockIdx.x;
    const int tid = threadIdx.x;
    const int len = lengths[b] - 1;   // valid positions [0, len)
    const float* sc = g_scores + b * SS;

    __shared__ float r1[256], r2[256];

    // pass 1: max
    float m = -FLT_MAX;
    for (int s = tid; s < len; s += 256) m = fmaxf(m, sc[s]);
    r1[tid] = m; __syncthreads();
    for (int off = 128; off > 0; off >>= 1) {
        if (tid < off) r1[tid] = fmaxf(r1[tid], r1[tid + off]);
        __syncthreads();
    }
    const float mx = r1[0];
    __syncthreads();

    // pass 2: sum exp, sum exp*score
    float s1 = 0.f, s2 = 0.f;
    for (int s = tid; s < len; s += 256) {
        float v = sc[s];
        float e = expf(v - mx);
        s1 += e; s2 += e * v;
    }
    r1[tid] = s1; r2[tid] = s2; __syncthreads();
    for (int off = 128; off > 0; off >>= 1) {
        if (tid < off) { r1[tid] += r1[tid + off]; r2[tid] += r2[tid + off]; }
        __syncthreads();
    }
    if (tid == 0) {
        float lse = mx + logf(r1[0]);
        out[0 * BN + b] = sc[pos_action[b]] - lse;   // logp_pos
        out[3 * BN + b] = lse - r2[0] / r1[0];       // ent_pos
    }
}

// ---------------------------------------------------------------------------
// Kernel C: symbol head -> logp_sym (row 1), ent_sym (row 4)
// ---------------------------------------------------------------------------
__global__ __launch_bounds__(256) void symbol_kernel(
    const float* __restrict__ states, const float* __restrict__ W1s,
    const float* __restrict__ b1s, const float* __restrict__ W2s,
    const float* __restrict__ b2s, const int* __restrict__ pos_action,
    const int* __restrict__ sym_action, float* __restrict__ out)
{
    const int b = blockIdx.x;
    const int tid = threadIdx.x;

    __shared__ float xs[KK];
    __shared__ float sh[KK];
    __shared__ float lg[AA];
    __shared__ float r1[128], r2[128];

    const int pa = pos_action[b];
    const float* xp = states + (size_t)b * SS * EE + (size_t)pa * EE;  // e1|e2 contiguous
    for (int i = tid; i < KK; i += 256) xs[i] = xp[i];
    __syncthreads();

    float a0 = b1s[tid], a1 = b1s[tid + 256], a2 = b1s[tid + 512], a3 = b1s[tid + 768];
    for (int k = 0; k < KK; ++k) {
        const float xk = xs[k];
        const float* wr = W1s + (size_t)k * KK;
        a0 = fmaf(xk, wr[tid],       a0);
        a1 = fmaf(xk, wr[tid + 256], a1);
        a2 = fmaf(xk, wr[tid + 512], a2);
        a3 = fmaf(xk, wr[tid + 768], a3);
    }
    sh[tid]       = fmaxf(a0, 0.f);
    sh[tid + 256] = fmaxf(a1, 0.f);
    sh[tid + 512] = fmaxf(a2, 0.f);
    sh[tid + 768] = fmaxf(a3, 0.f);
    __syncthreads();

    if (tid < AA) {
        float s = b2s[tid];
        for (int k = 0; k < KK; ++k) s = fmaf(sh[k], W2s[(size_t)k * AA + tid], s);
        lg[tid] = s;
    }
    __syncthreads();

    // softmax over 128 classes
    if (tid < 128) r1[tid] = lg[tid];
    __syncthreads();
    for (int off = 64; off > 0; off >>= 1) {
        if (tid < off) r1[tid] = fmaxf(r1[tid], r1[tid + off]);
        __syncthreads();
    }
    const float mx = r1[0];
    __syncthreads();
    if (tid < 128) {
        float e = expf(lg[tid] - mx);
        r1[tid] = e; r2[tid] = e * lg[tid];
    }
    __syncthreads();
    for (int off = 64; off > 0; off >>= 1) {
        if (tid < off) { r1[tid] += r1[tid + off]; r2[tid] += r2[tid + off]; }
        __syncthreads();
    }
    if (tid == 0) {
        float lse = mx + logf(r1[0]);
        out[1 * BN + b] = lg[sym_action[b]] - lse;   // logp_sym
        out[4 * BN + b] = lse - r2[0] / r1[0];       // ent_sym
    }
}

// ---------------------------------------------------------------------------
// Kernel D: value head -> val (row 2)
// ---------------------------------------------------------------------------
__global__ __launch_bounds__(256) void value_kernel(
    const float* __restrict__ cls, const float* __restrict__ Wc1,
    const float* __restrict__ bc1, const float* __restrict__ wc2,
    const float* __restrict__ bc2, float* __restrict__ out)
{
    const int b = blockIdx.x;
    const int tid = threadIdx.x;

    __shared__ float xs[EE];
    __shared__ float r1[256];

    const float* xp = cls + (size_t)b * EE;
    for (int i = tid; i < EE; i += 256) xs[i] = xp[i];
    __syncthreads();

    float a0 = bc1[tid], a1 = bc1[tid + 256];
    for (int k = 0; k < EE; ++k) {
        const float xk = xs[k];
        const float* wr = Wc1 + (size_t)k * EE;
        a0 = fmaf(xk, wr[tid],       a0);
        a1 = fmaf(xk, wr[tid + 256], a1);
    }
    r1[tid] = fmaxf(a0, 0.f) * wc2[tid] + fmaxf(a1, 0.f) * wc2[tid + 256];
    __syncthreads();
    for (int off = 128; off > 0; off >>= 1) {
        if (tid < off) r1[tid] += r1[tid + off];
        __syncthreads();
    }
    if (tid == 0) out[2 * BN + b] = r1[0] + bc2[0];
}

// ---------------------------------------------------------------------------
extern "C" void kernel_launch(void* const* d_in, const int* in_sizes, int n_in,
                              void* d_out, int out_size)
{
    const float* states     = (const float*)d_in[0];
    const float* cls_token  = (const float*)d_in[1];
    const float* W1p        = (const float*)d_in[2];
    const float* b1p        = (const float*)d_in[3];
    const float* w2p        = (const float*)d_in[4];
    // d_in[5] = b2p : constant shift, cancels in log_softmax
    const float* W1s        = (const float*)d_in[6];
    const float* b1s        = (const float*)d_in[7];
    const float* W2s        = (const float*)d_in[8];
    const float* b2s        = (const float*)d_in[9];
    const float* Wc1        = (const float*)d_in[10];
    const float* bc1        = (const float*)d_in[11];
    const float* wc2        = (const float*)d_in[12];
    const float* bc2        = (const float*)d_in[13];
    const int*   lengths    = (const int*)d_in[14];
    const int*   pos_action = (const int*)d_in[15];
    const int*   sym_action = (const int*)d_in[16];
    float* out = (float*)d_out;

    dim3 gA(16, BN);
    pos_scores_kernel<<<gA, 256>>>(states, W1p, b1p, w2p);
    pos_softmax_kernel<<<BN, 256>>>(lengths, pos_action, out);
    symbol_kernel<<<BN, 256>>>(states, W1s, b1s, W2s, b2s, pos_action, sym_action, out);
    value_kernel<<<BN, 256>>>(cls_token, Wc1, bc1, wc2, bc2, out);
}

// round 2
// speedup vs baseline: 1.0059x; 1.0059x over previous
#include <cuda_runtime.h>
#include <cfloat>
#include <cmath>

#define BN 64
#define SS 1024
#define EE 512
#define KK 1024   // 2*E
#define NN 1024   // 2*E
#define SM1 1023  // S-1
#define AA 128

// scratch: position scores (B x S, only first S-1 used per row)
__device__ float g_scores[BN * SS];

// ---------------------------------------------------------------------------
// Kernel A: fused scores = relu(X @ W1p + b1p) @ w2p
// X row (b,s) = 1024 contiguous floats at states[b, s, 0]
// grid: (16 s-tiles, 64 batches), 256 threads, 64x64 tile, K-tile 32
// ---------------------------------------------------------------------------
__global__ __launch_bounds__(256) void pos_scores_kernel(
    const float* __restrict__ states, const float* __restrict__ W1p,
    const float* __restrict__ b1p, const float* __restrict__ w2p)
{
    const int s0  = blockIdx.x * 64;
    const int b   = blockIdx.y;
    const int tid = threadIdx.x;
    const int tx  = tid & 15;
    const int ty  = tid >> 4;
    const int tx4 = tx * 4;
    const int ty4 = ty * 4;

    __shared__ float As[64][36];   // [m][k], row stride 144B (16B aligned)
    __shared__ float Bs[32][68];   // [k][f], row stride 272B (16B aligned)
    __shared__ float red[64][17];

    const float* Ab = states + (size_t)b * SS * EE;

    float ps[4] = {0.f, 0.f, 0.f, 0.f};

    const int a_ml = tid >> 3;          // 0..31
    const int a_kk = (tid & 7) * 4;     // 0..28
    const int b_kr = tid >> 4;          // 0..15
    const int b_fv = (tid & 15) * 4;    // 0..60

    for (int ntile = 0; ntile < 16; ++ntile) {
        const int f0 = ntile * 64;
        float acc[4][4] = {};

        for (int k0 = 0; k0 < KK; k0 += 32) {
            // load A tile 64x32 (clamp row so s=1023 stays in-bounds)
            #pragma unroll
            for (int it = 0; it < 2; ++it) {
                int m = a_ml + it * 32;
                int srow = s0 + m;
                if (srow > SS - 2) srow = SS - 2;
                float4 v = *(const float4*)(Ab + (size_t)srow * EE + (k0 + a_kk));
                *(float4*)&As[m][a_kk] = v;
            }
            // load B tile 32x64
            #pragma unroll
            for (int it = 0; it < 2; ++it) {
                int kr = b_kr + it * 16;
                float4 v = *(const float4*)(W1p + (size_t)(k0 + kr) * NN + f0 + b_fv);
                *(float4*)&Bs[kr][b_fv] = v;
            }
            __syncthreads();

            #pragma unroll
            for (int k = 0; k < 32; ++k) {
                float a0 = As[ty4 + 0][k];
                float a1 = As[ty4 + 1][k];
                float a2 = As[ty4 + 2][k];
                float a3 = As[ty4 + 3][k];
                float4 bv = *(const float4*)&Bs[k][tx4];
                acc[0][0] = fmaf(a0, bv.x, acc[0][0]);
                acc[0][1] = fmaf(a0, bv.y, acc[0][1]);
                acc[0][2] = fmaf(a0, bv.z, acc[0][2]);
                acc[0][3] = fmaf(a0, bv.w, acc[0][3]);
                acc[1][0] = fmaf(a1, bv.x, acc[1][0]);
                acc[1][1] = fmaf(a1, bv.y, acc[1][1]);
                acc[1][2] = fmaf(a1, bv.z, acc[1][2]);
                acc[1][3] = fmaf(a1, bv.w, acc[1][3]);
                acc[2][0] = fmaf(a2, bv.x, acc[2][0]);
                acc[2][1] = fmaf(a2, bv.y, acc[2][1]);
                acc[2][2] = fmaf(a2, bv.z, acc[2][2]);
                acc[2][3] = fmaf(a2, bv.w, acc[2][3]);
                acc[3][0] = fmaf(a3, bv.x, acc[3][0]);
                acc[3][1] = fmaf(a3, bv.y, acc[3][1]);
                acc[3][2] = fmaf(a3, bv.z, acc[3][2]);
                acc[3][3] = fmaf(a3, bv.w, acc[3][3]);
            }
            __syncthreads();
        }

        // fused epilogue: relu(pre + b1p) . w2p  (b2p dropped: softmax-invariant)
        float4 bias = *(const float4*)(b1p + f0 + tx4);
        float4 wv   = *(const float4*)(w2p + f0 + tx4);
        #pragma unroll
        for (int r = 0; r < 4; ++r) {
            ps[r] += fmaxf(acc[r][0] + bias.x, 0.f) * wv.x
                   + fmaxf(acc[r][1] + bias.y, 0.f) * wv.y
                   + fmaxf(acc[r][2] + bias.z, 0.f) * wv.z
                   + fmaxf(acc[r][3] + bias.w, 0.f) * wv.w;
        }
    }

    // reduce ps over the 16 tx lanes sharing each row (deterministic order)
    #pragma unroll
    for (int r = 0; r < 4; ++r) red[ty4 + r][tx] = ps[r];
    __syncthreads();
    if (tid < 64) {
        float s = 0.f;
        #pragma unroll
        for (int j = 0; j < 16; ++j) s += red[tid][j];
        int srow = s0 + tid;
        if (srow < SM1) g_scores[b * SS + srow] = s;
    }
}

// ---------------------------------------------------------------------------
// Kernel B: masked log-softmax over positions -> logp_pos (row 0), ent_pos (row 3)
// ---------------------------------------------------------------------------
__global__ __launch_bounds__(256) void pos_softmax_kernel(
    const int* __restrict__ lengths, const int* __restrict__ pos_action,
    float* __restrict__ out)
{
    const int b = blockIdx.x;
    const int tid = threadIdx.x;
    const int len = lengths[b] - 1;   // valid positions [0, len)
    const float* sc = g_scores + b * SS;

    __shared__ float r1[256], r2[256];

    // pass 1: max
    float m = -FLT_MAX;
    for (int s = tid; s < len; s += 256) m = fmaxf(m, sc[s]);
    r1[tid] = m; __syncthreads();
    for (int off = 128; off > 0; off >>= 1) {
        if (tid < off) r1[tid] = fmaxf(r1[tid], r1[tid + off]);
        __syncthreads();
    }
    const float mx = r1[0];
    __syncthreads();

    // pass 2: sum exp, sum exp*score
    float s1 = 0.f, s2 = 0.f;
    for (int s = tid; s < len; s += 256) {
        float v = sc[s];
        float e = expf(v - mx);
        s1 += e; s2 += e * v;
    }
    r1[tid] = s1; r2[tid] = s2; __syncthreads();
    for (int off = 128; off > 0; off >>= 1) {
        if (tid < off) { r1[tid] += r1[tid + off]; r2[tid] += r2[tid + off]; }
        __syncthreads();
    }
    if (tid == 0) {
        float lse = mx + logf(r1[0]);
        out[0 * BN + b] = sc[pos_action[b]] - lse;   // logp_pos
        out[3 * BN + b] = lse - r2[0] / r1[0];       // ent_pos
    }
}

// ---------------------------------------------------------------------------
// Kernel C: symbol head -> logp_sym (row 1), ent_sym (row 4)
// ---------------------------------------------------------------------------
__global__ __launch_bounds__(256) void symbol_kernel(
    const float* __restrict__ states, const float* __restrict__ W1s,
    const float* __restrict__ b1s, const float* __restrict__ W2s,
    const float* __restrict__ b2s, const int* __restrict__ pos_action,
    const int* __restrict__ sym_action, float* __restrict__ out)
{
    const int b = blockIdx.x;
    const int tid = threadIdx.x;

    __shared__ float xs[KK];
    __shared__ float sh[KK];
    __shared__ float lg[AA];
    __shared__ float r1[128], r2[128];

    const int pa = pos_action[b];
    const float* xp = states + (size_t)b * SS * EE + (size_t)pa * EE;  // e1|e2 contiguous
    for (int i = tid; i < KK; i += 256) xs[i] = xp[i];
    __syncthreads();

    float a0 = b1s[tid], a1 = b1s[tid + 256], a2 = b1s[tid + 512], a3 = b1s[tid + 768];
    for (int k = 0; k < KK; ++k) {
        const float xk = xs[k];
        const float* wr = W1s + (size_t)k * KK;
        a0 = fmaf(xk, wr[tid],       a0);
        a1 = fmaf(xk, wr[tid + 256], a1);
        a2 = fmaf(xk, wr[tid + 512], a2);
        a3 = fmaf(xk, wr[tid + 768], a3);
    }
    sh[tid]       = fmaxf(a0, 0.f);
    sh[tid + 256] = fmaxf(a1, 0.f);
    sh[tid + 512] = fmaxf(a2, 0.f);
    sh[tid + 768] = fmaxf(a3, 0.f);
    __syncthreads();

    if (tid < AA) {
        float s = b2s[tid];
        for (int k = 0; k < KK; ++k) s = fmaf(sh[k], W2s[(size_t)k * AA + tid], s);
        lg[tid] = s;
    }
    __syncthreads();

    // softmax over 128 classes
    if (tid < 128) r1[tid] = lg[tid];
    __syncthreads();
    for (int off = 64; off > 0; off >>= 1) {
        if (tid < off) r1[tid] = fmaxf(r1[tid], r1[tid + off]);
        __syncthreads();
    }
    const float mx = r1[0];
    __syncthreads();
    if (tid < 128) {
        float e = expf(lg[tid] - mx);
        r1[tid] = e; r2[tid] = e * lg[tid];
    }
    __syncthreads();
    for (int off = 64; off > 0; off >>= 1) {
        if (tid < off) { r1[tid] += r1[tid + off]; r2[tid] += r2[tid + off]; }
        __syncthreads();
    }
    if (tid == 0) {
        float lse = mx + logf(r1[0]);
        out[1 * BN + b] = lg[sym_action[b]] - lse;   // logp_sym
        out[4 * BN + b] = lse - r2[0] / r1[0];       // ent_sym
    }
}

// ---------------------------------------------------------------------------
// Kernel D: value head -> val (row 2)
// ---------------------------------------------------------------------------
__global__ __launch_bounds__(256) void value_kernel(
    const float* __restrict__ cls, const float* __restrict__ Wc1,
    const float* __restrict__ bc1, const float* __restrict__ wc2,
    const float* __restrict__ bc2, float* __restrict__ out)
{
    const int b = blockIdx.x;
    const int tid = threadIdx.x;

    __shared__ float xs[EE];
    __shared__ float r1[256];

    const float* xp = cls + (size_t)b * EE;
    for (int i = tid; i < EE; i += 256) xs[i] = xp[i];
    __syncthreads();

    float a0 = bc1[tid], a1 = bc1[tid + 256];
    for (int k = 0; k < EE; ++k) {
        const float xk = xs[k];
        const float* wr = Wc1 + (size_t)k * EE;
        a0 = fmaf(xk, wr[tid],       a0);
        a1 = fmaf(xk, wr[tid + 256], a1);
    }
    r1[tid] = fmaxf(a0, 0.f) * wc2[tid] + fmaxf(a1, 0.f) * wc2[tid + 256];
    __syncthreads();
    for (int off = 128; off > 0; off >>= 1) {
        if (tid < off) r1[tid] += r1[tid + off];
        __syncthreads();
    }
    if (tid == 0) out[2 * BN + b] = r1[0] + bc2[0];
}

// ---------------------------------------------------------------------------
extern "C" void kernel_launch(void* const* d_in, const int* in_sizes, int n_in,
                              void* d_out, int out_size)
{
    const float* states     = (const float*)d_in[0];
    const float* cls_token  = (const float*)d_in[1];
    const float* W1p        = (const float*)d_in[2];
    const float* b1p        = (const float*)d_in[3];
    const float* w2p        = (const float*)d_in[4];
    // d_in[5] = b2p : constant shift, cancels in log_softmax
    const float* W1s        = (const float*)d_in[6];
    const float* b1s        = (const float*)d_in[7];
    const float* W2s        = (const float*)d_in[8];
    const float* b2s        = (const float*)d_in[9];
    const float* Wc1        = (const float*)d_in[10];
    const float* bc1        = (const float*)d_in[11];
    const float* wc2        = (const float*)d_in[12];
    const float* bc2        = (const float*)d_in[13];
    const int*   lengths    = (const int*)d_in[14];
    const int*   pos_action = (const int*)d_in[15];
    const int*   sym_action = (const int*)d_in[16];
    float* out = (float*)d_out;

    dim3 gA(16, BN);
    pos_scores_kernel<<<gA, 256>>>(states, W1p, b1p, w2p);
    pos_softmax_kernel<<<BN, 256>>>(lengths, pos_action, out);
    symbol_kernel<<<BN, 256>>>(states, W1s, b1s, W2s, b2s, pos_action, sym_action, out);
    value_kernel<<<BN, 256>>>(cls_token, Wc1, bc1, wc2, bc2, out);
}

// round 4
// speedup vs baseline: 3.6388x; 3.6176x over previous
#include <cuda_runtime.h>
#include <cuda_bf16.h>
#include <cfloat>
#include <cmath>
#include <cstdint>

#define BN 64
#define SS 1024
#define EE 512
#define KK 1024
#define AA 128

// ------------------------- device scratch -------------------------
__device__ float g_scores[BN * SS];
__device__ float g_sh[BN * KK];
__device__ __align__(128) __nv_bfloat16 g_states_h[(size_t)BN * SS * EE + 1024]; // +pad (zero) for row 65535+1 reads
__device__ __align__(128) __nv_bfloat16 g_W1pT[(size_t)KK * KK];                 // [f][k]

// ------------------------- helpers -------------------------
__device__ __forceinline__ uint32_t smem_u32(const void* p) {
    uint32_t a;
    asm("{ .reg .u64 t; cvta.to.shared.u64 t, %1; cvt.u32.u64 %0, t; }" : "=r"(a) : "l"(p));
    return a;
}
__device__ __forceinline__ void cp_async16(uint32_t dst, const void* src) {
    asm volatile("cp.async.cg.shared.global [%0], [%1], 16;" :: "r"(dst), "l"(src) : "memory");
}
#define CP_COMMIT() asm volatile("cp.async.commit_group;" ::: "memory")
#define CP_WAIT1()  asm volatile("cp.async.wait_group 1;" ::: "memory")
#define CP_WAIT0()  asm volatile("cp.async.wait_group 0;" ::: "memory")

__device__ __forceinline__ void ldmx4(uint32_t* r, uint32_t addr) {
    asm volatile("ldmatrix.sync.aligned.m8n8.x4.shared.b16 {%0,%1,%2,%3}, [%4];"
        : "=r"(r[0]), "=r"(r[1]), "=r"(r[2]), "=r"(r[3]) : "r"(addr));
}
__device__ __forceinline__ void mma16816(float* c, const uint32_t* a, uint32_t b0, uint32_t b1) {
    asm volatile("mma.sync.aligned.m16n8k16.row.col.f32.bf16.bf16.f32 "
        "{%0,%1,%2,%3}, {%4,%5,%6,%7}, {%8,%9}, {%0,%1,%2,%3};"
        : "+f"(c[0]), "+f"(c[1]), "+f"(c[2]), "+f"(c[3])
        : "r"(a[0]), "r"(a[1]), "r"(a[2]), "r"(a[3]), "r"(b0), "r"(b1));
}

// ---------------------------------------------------------------------------
// Conversion kernels
// ---------------------------------------------------------------------------
__global__ __launch_bounds__(256) void conv_states_kernel(const float* __restrict__ s) {
    size_t i = ((size_t)blockIdx.x * 256 + threadIdx.x) * 8;
    float4 v0 = *(const float4*)(s + i);
    float4 v1 = *(const float4*)(s + i + 4);
    __nv_bfloat16 h[8];
    h[0] = __float2bfloat16(v0.x); h[1] = __float2bfloat16(v0.y);
    h[2] = __float2bfloat16(v0.z); h[3] = __float2bfloat16(v0.w);
    h[4] = __float2bfloat16(v1.x); h[5] = __float2bfloat16(v1.y);
    h[6] = __float2bfloat16(v1.z); h[7] = __float2bfloat16(v1.w);
    *(uint4*)(g_states_h + i) = *(uint4*)h;
}

__global__ void conv_w1pt_kernel(const float* __restrict__ W1p) {
    __shared__ __nv_bfloat16 t[32][33];
    const int bx = blockIdx.x, by = blockIdx.y;
    const int tx = threadIdx.x, ty = threadIdx.y;   // 32 x 8
    #pragma unroll
    for (int i = 0; i < 4; ++i)
        t[ty + i * 8][tx] = __float2bfloat16(W1p[(size_t)(by * 32 + ty + i * 8) * KK + bx * 32 + tx]);
    __syncthreads();
    #pragma unroll
    for (int i = 0; i < 4; ++i)
        g_W1pT[(size_t)(bx * 32 + ty + i * 8) * KK + by * 32 + tx] = t[tx][ty + i * 8];
}

// ---------------------------------------------------------------------------
// Kernel A: scores = relu(X @ W1p + b1p) . w2p  via mma.sync bf16 (HMMA)
// grid 512 (b*8 + stile), 256 thr = 8 warps (4M x 2N).
// M tile 128, N-chunks of 128 (8), K-chunks of 32, double-buffered cp.async.
// ---------------------------------------------------------------------------
#define TSTRIDE 40                 // smem row stride in halves (80B: 16B-aligned, conflict-free)
#define TILE_HALVES (128 * TSTRIDE)
#define TILE_BYTES  (TILE_HALVES * 2)

__global__ __launch_bounds__(256, 1) void pos_scores_mma(
    const float* __restrict__ b1p, const float* __restrict__ w2p)
{
    __shared__ __align__(16) __nv_bfloat16 Asm[2][TILE_HALVES];
    __shared__ __align__(16) __nv_bfloat16 Bsm[2][TILE_HALVES];
    __shared__ float red[128][2];

    const int tid  = threadIdx.x;
    const int lane = tid & 31;
    const int w    = tid >> 5;
    const int mw   = w & 3;        // M warp 0..3 (32 rows each)
    const int nw   = w >> 2;       // N warp 0..1 (64 cols each)
    const int bx   = blockIdx.x;
    const int b    = bx >> 3;
    const int s0   = (bx & 7) << 7;
    const int brow0 = (b << 10) + s0;

    const uint32_t Abase = smem_u32(Asm);
    const uint32_t Bbase = smem_u32(Bsm);

    // ldmatrix per-lane address components
    const int rA = (lane & 7) + 8 * ((lane >> 3) & 1);
    const int kA = 8 * (lane >> 4);
    const int rB = (lane & 7) + 8 * (lane >> 4);
    const int kB = 8 * ((lane >> 3) & 1);

    // cp.async per-thread assignments (2 A-chunks + 2 B-chunks of 16B)
    const int c0 = tid, c1 = 256 + tid;
    const int ar0 = c0 >> 2, as0 = c0 & 3;
    const int ar1 = c1 >> 2, as1 = c1 & 3;

    float acc[2][8][4];
    #pragma unroll
    for (int mt = 0; mt < 2; ++mt)
        #pragma unroll
        for (int nt = 0; nt < 8; ++nt)
            #pragma unroll
            for (int r = 0; r < 4; ++r) acc[mt][nt][r] = 0.f;
    float ps[2][2] = {{0.f, 0.f}, {0.f, 0.f}};

    // stage filler: global iter gg -> nc = gg>>5 (N chunk), k0 = (gg&31)*32
    auto fill = [&](int gg) {
        const int buf = gg & 1;
        const int n0  = (gg >> 5) * 128;
        const int k0  = (gg & 31) * 32;
        const uint32_t ab = Abase + buf * TILE_BYTES;
        const uint32_t bb = Bbase + buf * TILE_BYTES;
        cp_async16(ab + (ar0 * TSTRIDE + as0 * 8) * 2,
                   g_states_h + ((size_t)(brow0 + ar0) << 9) + k0 + as0 * 8);
        cp_async16(ab + (ar1 * TSTRIDE + as1 * 8) * 2,
                   g_states_h + ((size_t)(brow0 + ar1) << 9) + k0 + as1 * 8);
        cp_async16(bb + (ar0 * TSTRIDE + as0 * 8) * 2,
                   g_W1pT + ((size_t)(n0 + ar0) << 10) + k0 + as0 * 8);
        cp_async16(bb + (ar1 * TSTRIDE + as1 * 8) * 2,
                   g_W1pT + ((size_t)(n0 + ar1) << 10) + k0 + as1 * 8);
    };

    fill(0); CP_COMMIT();

    for (int g = 0; g < 256; ++g) {
        const int buf = g & 1;
        const int nc  = g >> 5;
        const int kit = g & 31;

        if (g + 1 < 256) { fill(g + 1); CP_COMMIT(); CP_WAIT1(); }
        else             { CP_WAIT0(); }
        __syncthreads();

        const uint32_t ab = Abase + buf * TILE_BYTES;
        const uint32_t bb = Bbase + buf * TILE_BYTES;

        #pragma unroll
        for (int h = 0; h < 2; ++h) {
            uint32_t af[2][4];
            #pragma unroll
            for (int mt = 0; mt < 2; ++mt)
                ldmx4(af[mt], ab + ((mw * 32 + mt * 16 + rA) * TSTRIDE + h * 16 + kA) * 2);
            uint32_t bf[4][4];
            #pragma unroll
            for (int bt = 0; bt < 4; ++bt)
                ldmx4(bf[bt], bb + ((nw * 64 + bt * 16 + rB) * TSTRIDE + h * 16 + kB) * 2);
            #pragma unroll
            for (int mt = 0; mt < 2; ++mt)
                #pragma unroll
                for (int nt = 0; nt < 8; ++nt)
                    mma16816(acc[mt][nt], af[mt], bf[nt >> 1][(nt & 1) * 2], bf[nt >> 1][(nt & 1) * 2 + 1]);
        }
        __syncthreads();   // stage consumed; safe to overwrite next iteration

        if (kit == 31) {
            // fused epilogue for this N-chunk: relu(acc + b1p) . w2p, row-reduce
            const int nbase = nc * 128 + nw * 64 + 2 * (lane & 3);
            #pragma unroll
            for (int mt = 0; mt < 2; ++mt) {
                float r0 = 0.f, r1 = 0.f;
                #pragma unroll
                for (int nt = 0; nt < 8; ++nt) {
                    const int n = nbase + nt * 8;
                    const float bb0 = __ldg(b1p + n),     ww0 = __ldg(w2p + n);
                    const float bb1 = __ldg(b1p + n + 1), ww1 = __ldg(w2p + n + 1);
                    r0 += fmaxf(acc[mt][nt][0] + bb0, 0.f) * ww0
                        + fmaxf(acc[mt][nt][1] + bb1, 0.f) * ww1;
                    r1 += fmaxf(acc[mt][nt][2] + bb0, 0.f) * ww0
                        + fmaxf(acc[mt][nt][3] + bb1, 0.f) * ww1;
                    acc[mt][nt][0] = acc[mt][nt][1] = acc[mt][nt][2] = acc[mt][nt][3] = 0.f;
                }
                r0 += __shfl_xor_sync(0xFFFFFFFFu, r0, 1);
                r0 += __shfl_xor_sync(0xFFFFFFFFu, r0, 2);
                r1 += __shfl_xor_sync(0xFFFFFFFFu, r1, 1);
                r1 += __shfl_xor_sync(0xFFFFFFFFu, r1, 2);
                ps[mt][0] += r0;
                ps[mt][1] += r1;
            }
        }
    }

    if ((lane & 3) == 0) {
        #pragma unroll
        for (int mt = 0; mt < 2; ++mt) {
            red[mw * 32 + mt * 16 + (lane >> 2)][nw]     = ps[mt][0];
            red[mw * 32 + mt * 16 + (lane >> 2) + 8][nw] = ps[mt][1];
        }
    }
    __syncthreads();
    if (tid < 128) {
        const int srow = s0 + tid;
        if (srow < SS - 1) g_scores[b * SS + srow] = red[tid][0] + red[tid][1];
    }
}

// ---------------------------------------------------------------------------
// Kernel B: masked log-softmax over positions -> rows 0, 3
// ---------------------------------------------------------------------------
__global__ __launch_bounds__(256) void pos_softmax_kernel(
    const int* __restrict__ lengths, const int* __restrict__ pos_action,
    float* __restrict__ out)
{
    const int b = blockIdx.x;
    const int tid = threadIdx.x;
    const int len = lengths[b] - 1;
    const float* sc = g_scores + b * SS;

    __shared__ float r1[256], r2[256];

    float m = -FLT_MAX;
    for (int s = tid; s < len; s += 256) m = fmaxf(m, sc[s]);
    r1[tid] = m; __syncthreads();
    for (int off = 128; off > 0; off >>= 1) {
        if (tid < off) r1[tid] = fmaxf(r1[tid], r1[tid + off]);
        __syncthreads();
    }
    const float mx = r1[0];
    __syncthreads();

    float s1 = 0.f, s2 = 0.f;
    for (int s = tid; s < len; s += 256) {
        float v = sc[s];
        float e = expf(v - mx);
        s1 += e; s2 += e * v;
    }
    r1[tid] = s1; r2[tid] = s2; __syncthreads();
    for (int off = 128; off > 0; off >>= 1) {
        if (tid < off) { r1[tid] += r1[tid + off]; r2[tid] += r2[tid + off]; }
        __syncthreads();
    }
    if (tid == 0) {
        float lse = mx + logf(r1[0]);
        out[0 * BN + b] = sc[pos_action[b]] - lse;
        out[3 * BN + b] = lse - r2[0] / r1[0];
    }
}

// ---------------------------------------------------------------------------
// Kernel C1: sh = relu(X @ W1s + b1s), two batches per block (W1s reuse)
// ---------------------------------------------------------------------------
__global__ __launch_bounds__(256) void symbol_h_kernel(
    const float* __restrict__ states, const float* __restrict__ W1s,
    const float* __restrict__ b1s, const int* __restrict__ pos_action)
{
    const int b0 = blockIdx.x * 2, b1 = b0 + 1;
    const int f = blockIdx.y * 256 + threadIdx.x;
    const int tid = threadIdx.x;

    __shared__ float xs0[KK], xs1[KK];
    const float* xp0 = states + (size_t)b0 * SS * EE + (size_t)pos_action[b0] * EE;
    const float* xp1 = states + (size_t)b1 * SS * EE + (size_t)pos_action[b1] * EE;
    for (int i = tid; i < KK; i += 256) { xs0[i] = xp0[i]; xs1[i] = xp1[i]; }
    __syncthreads();

    float a0 = b1s[f], a1 = a0;
    for (int k = 0; k < KK; ++k) {
        float wv = W1s[(size_t)k * KK + f];
        a0 = fmaf(xs0[k], wv, a0);
        a1 = fmaf(xs1[k], wv, a1);
    }
    g_sh[b0 * KK + f] = fmaxf(a0, 0.f);
    g_sh[b1 * KK + f] = fmaxf(a1, 0.f);
}

// ---------------------------------------------------------------------------
// Kernel C2: symbol logits + softmax -> rows 1, 4
// ---------------------------------------------------------------------------
__global__ __launch_bounds__(128) void symbol_logits_kernel(
    const float* __restrict__ W2s, const float* __restrict__ b2s,
    const int* __restrict__ sym_action, float* __restrict__ out)
{
    const int b = blockIdx.x;
    const int tid = threadIdx.x;

    __shared__ float sh[KK];
    __shared__ float lg[AA];
    __shared__ float r1[128], r2[128];

    for (int i = tid; i < KK; i += 128) sh[i] = g_sh[b * KK + i];
    __syncthreads();

    float s = b2s[tid];
    for (int k = 0; k < KK; ++k) s = fmaf(sh[k], W2s[(size_t)k * AA + tid], s);
    lg[tid] = s;
    r1[tid] = s;
    __syncthreads();
    for (int off = 64; off > 0; off >>= 1) {
        if (tid < off) r1[tid] = fmaxf(r1[tid], r1[tid + off]);
        __syncthreads();
    }
    const float mx = r1[0];
    __syncthreads();
    float e = expf(lg[tid] - mx);
    r1[tid] = e; r2[tid] = e * lg[tid];
    __syncthreads();
    for (int off = 64; off > 0; off >>= 1) {
        if (tid < off) { r1[tid] += r1[tid + off]; r2[tid] += r2[tid + off]; }
        __syncthreads();
    }
    if (tid == 0) {
        float lse = mx + logf(r1[0]);
        out[1 * BN + b] = lg[sym_action[b]] - lse;
        out[4 * BN + b] = lse - r2[0] / r1[0];
    }
}

// ---------------------------------------------------------------------------
// Kernel D: value head -> row 2
// ---------------------------------------------------------------------------
__global__ __launch_bounds__(512) void value_kernel(
    const float* __restrict__ cls, const float* __restrict__ Wc1,
    const float* __restrict__ bc1, const float* __restrict__ wc2,
    const float* __restrict__ bc2, float* __restrict__ out)
{
    const int b = blockIdx.x;
    const int tid = threadIdx.x;

    __shared__ float xs[EE];
    __shared__ float r1[512];

    xs[tid] = cls[(size_t)b * EE + tid];
    __syncthreads();

    float a = bc1[tid];
    #pragma unroll 8
    for (int k = 0; k < EE; ++k) a = fmaf(xs[k], Wc1[(size_t)k * EE + tid], a);
    r1[tid] = fmaxf(a, 0.f) * wc2[tid];
    __syncthreads();
    for (int off = 256; off > 0; off >>= 1) {
        if (tid < off) r1[tid] += r1[tid + off];
        __syncthreads();
    }
    if (tid == 0) out[2 * BN + b] = r1[0] + bc2[0];
}

// ---------------------------------------------------------------------------
extern "C" void kernel_launch(void* const* d_in, const int* in_sizes, int n_in,
                              void* d_out, int out_size)
{
    const float* states     = (const float*)d_in[0];
    const float* cls_token  = (const float*)d_in[1];
    const float* W1p        = (const float*)d_in[2];
    const float* b1p        = (const float*)d_in[3];
    const float* w2p        = (const float*)d_in[4];
    // d_in[5] = b2p : constant shift, cancels in log_softmax
    const float* W1s        = (const float*)d_in[6];
    const float* b1s        = (const float*)d_in[7];
    const float* W2s        = (const float*)d_in[8];
    const float* b2s        = (const float*)d_in[9];
    const float* Wc1        = (const float*)d_in[10];
    const float* bc1        = (const float*)d_in[11];
    const float* wc2        = (const float*)d_in[12];
    const float* bc2        = (const float*)d_in[13];
    const int*   lengths    = (const int*)d_in[14];
    const int*   pos_action = (const int*)d_in[15];
    const int*   sym_action = (const int*)d_in[16];
    float* out = (float*)d_out;

    conv_states_kernel<<<16384, 256>>>(states);
    conv_w1pt_kernel<<<dim3(32, 32), dim3(32, 8)>>>(W1p);
    pos_scores_mma<<<512, 256>>>(b1p, w2p);
    pos_softmax_kernel<<<BN, 256>>>(lengths, pos_action, out);
    symbol_h_kernel<<<dim3(32, 4), 256>>>(states, W1s, b1s, pos_action);
    symbol_logits_kernel<<<BN, 128>>>(W2s, b2s, sym_action, out);
    value_kernel<<<BN, 512>>>(cls_token, Wc1, bc1, wc2, bc2, out);
}

// round 5
// speedup vs baseline: 4.7337x; 1.3009x over previous
#include <cuda_runtime.h>
#include <cuda_bf16.h>
#include <cfloat>
#include <cmath>
#include <cstdint>

#define BN 64
#define SS 1024
#define EE 512
#define KK 1024
#define AA 128

// ------------------------- device scratch -------------------------
__device__ float g_scores[BN * SS];
__device__ float g_sh[BN * KK];
__device__ __align__(128) __nv_bfloat16 g_states_h[(size_t)BN * SS * EE + 1024]; // +pad for (b=63,s=1023) tail row
__device__ __align__(128) __nv_bfloat16 g_W1pT[(size_t)KK * KK];                 // [f][k]

// ------------------------- helpers -------------------------
__device__ __forceinline__ uint32_t smem_u32(const void* p) {
    uint32_t a;
    asm("{ .reg .u64 t; cvta.to.shared.u64 t, %1; cvt.u32.u64 %0, t; }" : "=r"(a) : "l"(p));
    return a;
}
__device__ __forceinline__ void cp_async16(uint32_t dst, const void* src) {
    asm volatile("cp.async.cg.shared.global [%0], [%1], 16;" :: "r"(dst), "l"(src) : "memory");
}
#define CP_COMMIT() asm volatile("cp.async.commit_group;" ::: "memory")
#define CP_WAIT1()  asm volatile("cp.async.wait_group 1;" ::: "memory")
#define CP_WAIT0()  asm volatile("cp.async.wait_group 0;" ::: "memory")

__device__ __forceinline__ void ldmx4(uint32_t* r, uint32_t addr) {
    asm volatile("ldmatrix.sync.aligned.m8n8.x4.shared.b16 {%0,%1,%2,%3}, [%4];"
        : "=r"(r[0]), "=r"(r[1]), "=r"(r[2]), "=r"(r[3]) : "r"(addr));
}
__device__ __forceinline__ void mma16816(float* c, const uint32_t* a, uint32_t b0, uint32_t b1) {
    asm volatile("mma.sync.aligned.m16n8k16.row.col.f32.bf16.bf16.f32 "
        "{%0,%1,%2,%3}, {%4,%5,%6,%7}, {%8,%9}, {%0,%1,%2,%3};"
        : "+f"(c[0]), "+f"(c[1]), "+f"(c[2]), "+f"(c[3])
        : "r"(a[0]), "r"(a[1]), "r"(a[2]), "r"(a[3]), "r"(b0), "r"(b1));
}

// ---------------------------------------------------------------------------
// Conversion kernels
// ---------------------------------------------------------------------------
__global__ __launch_bounds__(256) void conv_states_kernel(const float* __restrict__ s) {
    size_t i = ((size_t)blockIdx.x * 256 + threadIdx.x) * 8;
    float4 v0 = *(const float4*)(s + i);
    float4 v1 = *(const float4*)(s + i + 4);
    __nv_bfloat16 h[8];
    h[0] = __float2bfloat16(v0.x); h[1] = __float2bfloat16(v0.y);
    h[2] = __float2bfloat16(v0.z); h[3] = __float2bfloat16(v0.w);
    h[4] = __float2bfloat16(v1.x); h[5] = __float2bfloat16(v1.y);
    h[6] = __float2bfloat16(v1.z); h[7] = __float2bfloat16(v1.w);
    *(uint4*)(g_states_h + i) = *(uint4*)h;
}

__global__ void conv_w1pt_kernel(const float* __restrict__ W1p) {
    __shared__ __nv_bfloat16 t[32][33];
    const int bx = blockIdx.x, by = blockIdx.y;
    const int tx = threadIdx.x, ty = threadIdx.y;   // 32 x 8
    #pragma unroll
    for (int i = 0; i < 4; ++i)
        t[ty + i * 8][tx] = __float2bfloat16(W1p[(size_t)(by * 32 + ty + i * 8) * KK + bx * 32 + tx]);
    __syncthreads();
    #pragma unroll
    for (int i = 0; i < 4; ++i)
        g_W1pT[(size_t)(bx * 32 + ty + i * 8) * KK + by * 32 + tx] = t[tx][ty + i * 8];
}

// ---------------------------------------------------------------------------
// Kernel A: scores = relu(X @ W1p + b1p) . w2p  via mma.sync bf16 (HMMA)
// grid 512 (b*8 + stile), 256 thr = 8 warps (4M x 2N), 2 CTAs/SM.
// M tile 128, N-chunks of 128 (8), K-chunk 64 (16 iters/chunk), double buffer.
// ---------------------------------------------------------------------------
#define KCH 64
#define TSTRIDE 72                    // halves: 144B row, 16B aligned, ldmatrix conflict-free
#define TILE_HALVES (128 * TSTRIDE)
#define TILE_BYTES  (TILE_HALVES * 2) // 18432
#define STAGE_BYTES (2 * TILE_BYTES)  // 36864 (A + B)
#define RED_OFF     (2 * STAGE_BYTES) // 73728
#define DSM_TOTAL   (RED_OFF + 128 * 2 * 4)

extern __shared__ char dsm[];

__global__ __launch_bounds__(256, 2) void pos_scores_mma(
    const float* __restrict__ b1p, const float* __restrict__ w2p)
{
    const int tid  = threadIdx.x;
    const int lane = tid & 31;
    const int w    = tid >> 5;
    const int mw   = w & 3;        // M warp 0..3 (32 rows each)
    const int nw   = w >> 2;       // N warp 0..1 (64 cols each)
    const int bx   = blockIdx.x;
    const int b    = bx >> 3;
    const int s0   = (bx & 7) << 7;
    const int brow0 = (b << 10) + s0;

    const uint32_t base = smem_u32(dsm);
    float* red = (float*)(dsm + RED_OFF);

    // ldmatrix per-lane address components
    const int rA = (lane & 7) + 8 * ((lane >> 3) & 1);
    const int kA = 8 * (lane >> 4);
    const int rB = (lane & 7) + 8 * (lane >> 4);
    const int kB = 8 * ((lane >> 3) & 1);

    float acc[2][8][4];
    #pragma unroll
    for (int mt = 0; mt < 2; ++mt)
        #pragma unroll
        for (int nt = 0; nt < 8; ++nt)
            #pragma unroll
            for (int r = 0; r < 4; ++r) acc[mt][nt][r] = 0.f;
    float ps[2][2] = {{0.f, 0.f}, {0.f, 0.f}};

    // stage filler: gg -> nc = gg>>4 (N chunk), k0 = (gg&15)*64
    auto fill = [&](int gg) {
        const int buf = gg & 1;
        const int n0  = (gg >> 4) << 7;
        const int k0  = (gg & 15) << 6;
        const uint32_t ab = base + buf * STAGE_BYTES;
        const uint32_t bb = ab + TILE_BYTES;
        #pragma unroll
        for (int i = 0; i < 4; ++i) {
            const int c = i * 256 + tid;         // 0..1023
            const int row = c >> 3, seg = c & 7;
            const uint32_t doff = (row * TSTRIDE + seg * 8) * 2;
            cp_async16(ab + doff, g_states_h + ((size_t)(brow0 + row) << 9) + k0 + seg * 8);
            cp_async16(bb + doff, g_W1pT + ((size_t)(n0 + row) << 10) + k0 + seg * 8);
        }
    };

    fill(0); CP_COMMIT();

    for (int g = 0; g < 128; ++g) {
        const int buf = g & 1;
        const int nc  = g >> 4;
        const int kit = g & 15;

        if (g + 1 < 128) { fill(g + 1); CP_COMMIT(); CP_WAIT1(); }
        else             { CP_WAIT0(); }
        __syncthreads();

        const uint32_t ab = base + buf * STAGE_BYTES;
        const uint32_t bb = ab + TILE_BYTES;

        #pragma unroll
        for (int h = 0; h < 4; ++h) {
            uint32_t af[2][4];
            #pragma unroll
            for (int mt = 0; mt < 2; ++mt)
                ldmx4(af[mt], ab + ((mw * 32 + mt * 16 + rA) * TSTRIDE + h * 16 + kA) * 2);
            uint32_t bf[4][4];
            #pragma unroll
            for (int bt = 0; bt < 4; ++bt)
                ldmx4(bf[bt], bb + ((nw * 64 + bt * 16 + rB) * TSTRIDE + h * 16 + kB) * 2);
            #pragma unroll
            for (int mt = 0; mt < 2; ++mt)
                #pragma unroll
                for (int nt = 0; nt < 8; ++nt)
                    mma16816(acc[mt][nt], af[mt], bf[nt >> 1][(nt & 1) * 2], bf[nt >> 1][(nt & 1) * 2 + 1]);
        }
        __syncthreads();   // stage consumed; safe to refill next iteration

        if (kit == 15) {
            // fused epilogue for this N-chunk: relu(acc + b1p) . w2p, row-reduce
            const int nbase = nc * 128 + nw * 64 + 2 * (lane & 3);
            #pragma unroll
            for (int mt = 0; mt < 2; ++mt) {
                float r0 = 0.f, r1 = 0.f;
                #pragma unroll
                for (int nt = 0; nt < 8; ++nt) {
                    const int n = nbase + nt * 8;
                    const float bb0 = __ldg(b1p + n),     ww0 = __ldg(w2p + n);
                    const float bb1 = __ldg(b1p + n + 1), ww1 = __ldg(w2p + n + 1);
                    r0 += fmaxf(acc[mt][nt][0] + bb0, 0.f) * ww0
                        + fmaxf(acc[mt][nt][1] + bb1, 0.f) * ww1;
                    r1 += fmaxf(acc[mt][nt][2] + bb0, 0.f) * ww0
                        + fmaxf(acc[mt][nt][3] + bb1, 0.f) * ww1;
                    acc[mt][nt][0] = acc[mt][nt][1] = acc[mt][nt][2] = acc[mt][nt][3] = 0.f;
                }
                r0 += __shfl_xor_sync(0xFFFFFFFFu, r0, 1);
                r0 += __shfl_xor_sync(0xFFFFFFFFu, r0, 2);
                r1 += __shfl_xor_sync(0xFFFFFFFFu, r1, 1);
                r1 += __shfl_xor_sync(0xFFFFFFFFu, r1, 2);
                ps[mt][0] += r0;
                ps[mt][1] += r1;
            }
        }
    }

    if ((lane & 3) == 0) {
        #pragma unroll
        for (int mt = 0; mt < 2; ++mt) {
            red[(mw * 32 + mt * 16 + (lane >> 2)) * 2 + nw]       = ps[mt][0];
            red[(mw * 32 + mt * 16 + (lane >> 2) + 8) * 2 + nw]   = ps[mt][1];
        }
    }
    __syncthreads();
    if (tid < 128) {
        const int srow = s0 + tid;
        if (srow < SS - 1) g_scores[b * SS + srow] = red[tid * 2] + red[tid * 2 + 1];
    }
}

// ---------------------------------------------------------------------------
// Kernel B: masked log-softmax over positions -> rows 0, 3
// ---------------------------------------------------------------------------
__global__ __launch_bounds__(256) void pos_softmax_kernel(
    const int* __restrict__ lengths, const int* __restrict__ pos_action,
    float* __restrict__ out)
{
    const int b = blockIdx.x;
    const int tid = threadIdx.x;
    const int len = lengths[b] - 1;
    const float* sc = g_scores + b * SS;

    __shared__ float r1[256], r2[256];

    float m = -FLT_MAX;
    for (int s = tid; s < len; s += 256) m = fmaxf(m, sc[s]);
    r1[tid] = m; __syncthreads();
    for (int off = 128; off > 0; off >>= 1) {
        if (tid < off) r1[tid] = fmaxf(r1[tid], r1[tid + off]);
        __syncthreads();
    }
    const float mx = r1[0];
    __syncthreads();

    float s1 = 0.f, s2 = 0.f;
    for (int s = tid; s < len; s += 256) {
        float v = sc[s];
        float e = expf(v - mx);
        s1 += e; s2 += e * v;
    }
    r1[tid] = s1; r2[tid] = s2; __syncthreads();
    for (int off = 128; off > 0; off >>= 1) {
        if (tid < off) { r1[tid] += r1[tid + off]; r2[tid] += r2[tid + off]; }
        __syncthreads();
    }
    if (tid == 0) {
        float lse = mx + logf(r1[0]);
        out[0 * BN + b] = sc[pos_action[b]] - lse;
        out[3 * BN + b] = lse - r2[0] / r1[0];
    }
}

// ---------------------------------------------------------------------------
// Kernel C1: sh = relu(X @ W1s + b1s), FOUR batches per block (W1s reuse)
// grid (16, 4), 256 threads
// ---------------------------------------------------------------------------
__global__ __launch_bounds__(256) void symbol_h_kernel(
    const float* __restrict__ states, const float* __restrict__ W1s,
    const float* __restrict__ b1s, const int* __restrict__ pos_action)
{
    const int bb = blockIdx.x * 4;
    const int f = blockIdx.y * 256 + threadIdx.x;
    const int tid = threadIdx.x;

    __shared__ float xs[4][KK];
    #pragma unroll
    for (int j = 0; j < 4; ++j) {
        const float* xp = states + (size_t)(bb + j) * SS * EE + (size_t)pos_action[bb + j] * EE;
        for (int i = tid; i < KK; i += 256) xs[j][i] = xp[i];
    }
    __syncthreads();

    const float bias = b1s[f];
    float a0 = bias, a1 = bias, a2 = bias, a3 = bias;
    for (int k = 0; k < KK; ++k) {
        const float wv = W1s[(size_t)k * KK + f];
        a0 = fmaf(xs[0][k], wv, a0);
        a1 = fmaf(xs[1][k], wv, a1);
        a2 = fmaf(xs[2][k], wv, a2);
        a3 = fmaf(xs[3][k], wv, a3);
    }
    g_sh[(bb + 0) * KK + f] = fmaxf(a0, 0.f);
    g_sh[(bb + 1) * KK + f] = fmaxf(a1, 0.f);
    g_sh[(bb + 2) * KK + f] = fmaxf(a2, 0.f);
    g_sh[(bb + 3) * KK + f] = fmaxf(a3, 0.f);
}

// ---------------------------------------------------------------------------
// Kernel C2: symbol logits + softmax -> rows 1, 4
// ---------------------------------------------------------------------------
__global__ __launch_bounds__(128) void symbol_logits_kernel(
    const float* __restrict__ W2s, const float* __restrict__ b2s,
    const int* __restrict__ sym_action, float* __restrict__ out)
{
    const int b = blockIdx.x;
    const int tid = threadIdx.x;

    __shared__ float sh[KK];
    __shared__ float lg[AA];
    __shared__ float r1[128], r2[128];

    for (int i = tid; i < KK; i += 128) sh[i] = g_sh[b * KK + i];
    __syncthreads();

    float s = b2s[tid];
    for (int k = 0; k < KK; ++k) s = fmaf(sh[k], W2s[(size_t)k * AA + tid], s);
    lg[tid] = s;
    r1[tid] = s;
    __syncthreads();
    for (int off = 64; off > 0; off >>= 1) {
        if (tid < off) r1[tid] = fmaxf(r1[tid], r1[tid + off]);
        __syncthreads();
    }
    const float mx = r1[0];
    __syncthreads();
    float e = expf(lg[tid] - mx);
    r1[tid] = e; r2[tid] = e * lg[tid];
    __syncthreads();
    for (int off = 64; off > 0; off >>= 1) {
        if (tid < off) { r1[tid] += r1[tid + off]; r2[tid] += r2[tid + off]; }
        __syncthreads();
    }
    if (tid == 0) {
        float lse = mx + logf(r1[0]);
        out[1 * BN + b] = lg[sym_action[b]] - lse;
        out[4 * BN + b] = lse - r2[0] / r1[0];
    }
}

// ---------------------------------------------------------------------------
// Kernel D: value head -> row 2 (4 batches per block, Wc1 reuse)
// grid 16, 512 threads
// ---------------------------------------------------------------------------
__global__ __launch_bounds__(512) void value_kernel(
    const float* __restrict__ cls, const float* __restrict__ Wc1,
    const float* __restrict__ bc1, const float* __restrict__ wc2,
    const float* __restrict__ bc2, float* __restrict__ out)
{
    const int bb = blockIdx.x * 4;
    const int tid = threadIdx.x;

    __shared__ float xs[4][EE];
    __shared__ float red[4][512];

    #pragma unroll
    for (int j = 0; j < 4; ++j)
        if (tid < EE) xs[j][tid] = cls[(size_t)(bb + j) * EE + tid];
    __syncthreads();

    const float bias = bc1[tid];
    float a0 = bias, a1 = bias, a2 = bias, a3 = bias;
    #pragma unroll 4
    for (int k = 0; k < EE; ++k) {
        const float wv = Wc1[(size_t)k * EE + tid];
        a0 = fmaf(xs[0][k], wv, a0);
        a1 = fmaf(xs[1][k], wv, a1);
        a2 = fmaf(xs[2][k], wv, a2);
        a3 = fmaf(xs[3][k], wv, a3);
    }
    const float wc = wc2[tid];
    red[0][tid] = fmaxf(a0, 0.f) * wc;
    red[1][tid] = fmaxf(a1, 0.f) * wc;
    red[2][tid] = fmaxf(a2, 0.f) * wc;
    red[3][tid] = fmaxf(a3, 0.f) * wc;
    __syncthreads();
    for (int off = 256; off > 0; off >>= 1) {
        if (tid < off) {
            red[0][tid] += red[0][tid + off];
            red[1][tid] += red[1][tid + off];
            red[2][tid] += red[2][tid + off];
            red[3][tid] += red[3][tid + off];
        }
        __syncthreads();
    }
    if (tid < 4) out[2 * BN + bb + tid] = red[tid][0] + bc2[0];
}

// ---------------------------------------------------------------------------
extern "C" void kernel_launch(void* const* d_in, const int* in_sizes, int n_in,
                              void* d_out, int out_size)
{
    const float* states     = (const float*)d_in[0];
    const float* cls_token  = (const float*)d_in[1];
    const float* W1p        = (const float*)d_in[2];
    const float* b1p        = (const float*)d_in[3];
    const float* w2p        = (const float*)d_in[4];
    // d_in[5] = b2p : constant shift, cancels in log_softmax
    const float* W1s        = (const float*)d_in[6];
    const float* b1s        = (const float*)d_in[7];
    const float* W2s        = (const float*)d_in[8];
    const float* b2s        = (const float*)d_in[9];
    const float* Wc1        = (const float*)d_in[10];
    const float* bc1        = (const float*)d_in[11];
    const float* wc2        = (const float*)d_in[12];
    const float* bc2        = (const float*)d_in[13];
    const int*   lengths    = (const int*)d_in[14];
    const int*   pos_action = (const int*)d_in[15];
    const int*   sym_action = (const int*)d_in[16];
    float* out = (float*)d_out;

    static int configured = 0;
    if (!configured) {
        cudaFuncSetAttribute(pos_scores_mma, cudaFuncAttributeMaxDynamicSharedMemorySize, DSM_TOTAL);
        configured = 1;
    }

    conv_states_kernel<<<16384, 256>>>(states);
    conv_w1pt_kernel<<<dim3(32, 32), dim3(32, 8)>>>(W1p);
    pos_scores_mma<<<512, 256, DSM_TOTAL>>>(b1p, w2p);
    pos_softmax_kernel<<<BN, 256>>>(lengths, pos_action, out);
    symbol_h_kernel<<<dim3(16, 4), 256>>>(states, W1s, b1s, pos_action);
    symbol_logits_kernel<<<BN, 128>>>(W2s, b2s, sym_action, out);
    value_kernel<<<16, 512>>>(cls_token, Wc1, bc1, wc2, bc2, out);
}

// round 6
// speedup vs baseline: 4.7778x; 1.0093x over previous
#include <cuda_runtime.h>
#include <cuda_bf16.h>
#include <cfloat>
#include <cmath>
#include <cstdint>

#define BN 64
#define SS 1024
#define EE 512
#define KK 1024
#define AA 128

// ------------------------- device scratch -------------------------
__device__ float g_scores[BN * SS];
__device__ float g_sh[BN * KK];
__device__ __align__(128) __nv_bfloat16 g_states_h[(size_t)BN * SS * EE + 1024]; // +pad for (b=63,s=1023) tail row
__device__ __align__(128) __nv_bfloat16 g_W1pT[(size_t)KK * KK];                 // [f][k]

// ------------------------- helpers -------------------------
__device__ __forceinline__ uint32_t smem_u32(const void* p) {
    uint32_t a;
    asm("{ .reg .u64 t; cvta.to.shared.u64 t, %1; cvt.u32.u64 %0, t; }" : "=r"(a) : "l"(p));
    return a;
}
__device__ __forceinline__ void cp_async16(uint32_t dst, const void* src) {
    asm volatile("cp.async.cg.shared.global [%0], [%1], 16;" :: "r"(dst), "l"(src) : "memory");
}
#define CP_COMMIT() asm volatile("cp.async.commit_group;" ::: "memory")
#define CP_WAIT1()  asm volatile("cp.async.wait_group 1;" ::: "memory")
#define CP_WAIT0()  asm volatile("cp.async.wait_group 0;" ::: "memory")

__device__ __forceinline__ void ldmx4(uint32_t* r, uint32_t addr) {
    asm volatile("ldmatrix.sync.aligned.m8n8.x4.shared.b16 {%0,%1,%2,%3}, [%4];"
        : "=r"(r[0]), "=r"(r[1]), "=r"(r[2]), "=r"(r[3]) : "r"(addr));
}
__device__ __forceinline__ void mma16816(float* c, const uint32_t* a, uint32_t b0, uint32_t b1) {
    asm volatile("mma.sync.aligned.m16n8k16.row.col.f32.bf16.bf16.f32 "
        "{%0,%1,%2,%3}, {%4,%5,%6,%7}, {%8,%9}, {%0,%1,%2,%3};"
        : "+f"(c[0]), "+f"(c[1]), "+f"(c[2]), "+f"(c[3])
        : "r"(a[0]), "r"(a[1]), "r"(a[2]), "r"(a[3]), "r"(b0), "r"(b1));
}

// ---------------------------------------------------------------------------
// Conversion kernels
// ---------------------------------------------------------------------------
__global__ __launch_bounds__(256) void conv_states_kernel(const float* __restrict__ s) {
    size_t i = ((size_t)blockIdx.x * 256 + threadIdx.x) * 8;
    float4 v0 = *(const float4*)(s + i);
    float4 v1 = *(const float4*)(s + i + 4);
    __nv_bfloat16 h[8];
    h[0] = __float2bfloat16(v0.x); h[1] = __float2bfloat16(v0.y);
    h[2] = __float2bfloat16(v0.z); h[3] = __float2bfloat16(v0.w);
    h[4] = __float2bfloat16(v1.x); h[5] = __float2bfloat16(v1.y);
    h[6] = __float2bfloat16(v1.z); h[7] = __float2bfloat16(v1.w);
    *(uint4*)(g_states_h + i) = *(uint4*)h;
}

__global__ void conv_w1pt_kernel(const float* __restrict__ W1p) {
    __shared__ __nv_bfloat16 t[32][33];
    const int bx = blockIdx.x, by = blockIdx.y;
    const int tx = threadIdx.x, ty = threadIdx.y;   // 32 x 8
    #pragma unroll
    for (int i = 0; i < 4; ++i)
        t[ty + i * 8][tx] = __float2bfloat16(W1p[(size_t)(by * 32 + ty + i * 8) * KK + bx * 32 + tx]);
    __syncthreads();
    #pragma unroll
    for (int i = 0; i < 4; ++i)
        g_W1pT[(size_t)(bx * 32 + ty + i * 8) * KK + by * 32 + tx] = t[tx][ty + i * 8];
}

// ---------------------------------------------------------------------------
// Kernel A: scores = relu(X @ W1p + b1p) . w2p  via mma.sync bf16 (HMMA)
// grid 512 (b*8 + stile), 256 thr = 8 warps (4M x 2N), 2 CTAs/SM.
// M tile 128, N-chunks of 128 (8), K-chunk 64.
// 3-stage cp.async ring, prefetch distance 2, ONE barrier per iteration.
// ---------------------------------------------------------------------------
#define TSTRIDE 72                    // halves: 144B row, 16B aligned, ldmatrix conflict-free
#define TILE_HALVES (128 * TSTRIDE)
#define TILE_BYTES  (TILE_HALVES * 2) // 18432
#define STAGE_BYTES (2 * TILE_BYTES)  // 36864 (A + B)
#define NSTAGE 3
#define RED_OFF     (NSTAGE * STAGE_BYTES) // 110592
#define DSM_TOTAL   (RED_OFF + 128 * 2 * 4)

extern __shared__ char dsm[];

__global__ __launch_bounds__(256, 2) void pos_scores_mma(
    const float* __restrict__ b1p, const float* __restrict__ w2p)
{
    const int tid  = threadIdx.x;
    const int lane = tid & 31;
    const int w    = tid >> 5;
    const int mw   = w & 3;        // M warp 0..3 (32 rows each)
    const int nw   = w >> 2;       // N warp 0..1 (64 cols each)
    const int bx   = blockIdx.x;
    const int b    = bx >> 3;
    const int s0   = (bx & 7) << 7;
    const int brow0 = (b << 10) + s0;

    const uint32_t base = smem_u32(dsm);
    float* red = (float*)(dsm + RED_OFF);

    // ldmatrix per-lane address components
    const int rA = (lane & 7) + 8 * ((lane >> 3) & 1);
    const int kA = 8 * (lane >> 4);
    const int rB = (lane & 7) + 8 * (lane >> 4);
    const int kB = 8 * ((lane >> 3) & 1);

    float acc[2][8][4];
    #pragma unroll
    for (int mt = 0; mt < 2; ++mt)
        #pragma unroll
        for (int nt = 0; nt < 8; ++nt)
            #pragma unroll
            for (int r = 0; r < 4; ++r) acc[mt][nt][r] = 0.f;
    float ps[2][2] = {{0.f, 0.f}, {0.f, 0.f}};

    // stage filler: gg -> nc = gg>>4 (N chunk), k0 = (gg&15)*64; buf given explicitly
    auto fill = [&](int gg, int buf) {
        const int n0  = (gg >> 4) << 7;
        const int k0  = (gg & 15) << 6;
        const uint32_t ab = base + buf * STAGE_BYTES;
        const uint32_t bb = ab + TILE_BYTES;
        #pragma unroll
        for (int i = 0; i < 4; ++i) {
            const int c = i * 256 + tid;         // 0..1023
            const int row = c >> 3, seg = c & 7;
            const uint32_t doff = (row * TSTRIDE + seg * 8) * 2;
            cp_async16(ab + doff, g_states_h + ((size_t)(brow0 + row) << 9) + k0 + seg * 8);
            cp_async16(bb + doff, g_W1pT + ((size_t)(n0 + row) << 10) + k0 + seg * 8);
        }
    };

    fill(0, 0); CP_COMMIT();
    fill(1, 1); CP_COMMIT();

    int buf = 0;        // stage holding iteration g
    int buf2 = 2;       // stage to fill with g+2

    for (int g = 0; g < 128; ++g) {
        const int nc  = g >> 4;
        const int kit = g & 15;

        // ensure fill(g) landed (g+1 may still be in flight)
        if (g == 127) { CP_WAIT0(); } else { CP_WAIT1(); }
        __syncthreads();   // all warps past compute(g-1); buffer buf2 is reusable

        if (g + 2 < 128) { fill(g + 2, buf2); CP_COMMIT(); }

        const uint32_t ab = base + buf * STAGE_BYTES;
        const uint32_t bb = ab + TILE_BYTES;

        #pragma unroll
        for (int h = 0; h < 4; ++h) {
            uint32_t af[2][4];
            #pragma unroll
            for (int mt = 0; mt < 2; ++mt)
                ldmx4(af[mt], ab + ((mw * 32 + mt * 16 + rA) * TSTRIDE + h * 16 + kA) * 2);
            uint32_t bf[4][4];
            #pragma unroll
            for (int bt = 0; bt < 4; ++bt)
                ldmx4(bf[bt], bb + ((nw * 64 + bt * 16 + rB) * TSTRIDE + h * 16 + kB) * 2);
            #pragma unroll
            for (int mt = 0; mt < 2; ++mt)
                #pragma unroll
                for (int nt = 0; nt < 8; ++nt)
                    mma16816(acc[mt][nt], af[mt], bf[nt >> 1][(nt & 1) * 2], bf[nt >> 1][(nt & 1) * 2 + 1]);
        }

        if (kit == 15) {
            // fused epilogue for this N-chunk: relu(acc + b1p) . w2p, row-reduce
            const int nbase = nc * 128 + nw * 64 + 2 * (lane & 3);
            #pragma unroll
            for (int mt = 0; mt < 2; ++mt) {
                float r0 = 0.f, r1 = 0.f;
                #pragma unroll
                for (int nt = 0; nt < 8; ++nt) {
                    const int n = nbase + nt * 8;
                    const float bb0 = __ldg(b1p + n),     ww0 = __ldg(w2p + n);
                    const float bb1 = __ldg(b1p + n + 1), ww1 = __ldg(w2p + n + 1);
                    r0 += fmaxf(acc[mt][nt][0] + bb0, 0.f) * ww0
                        + fmaxf(acc[mt][nt][1] + bb1, 0.f) * ww1;
                    r1 += fmaxf(acc[mt][nt][2] + bb0, 0.f) * ww0
                        + fmaxf(acc[mt][nt][3] + bb1, 0.f) * ww1;
                    acc[mt][nt][0] = acc[mt][nt][1] = acc[mt][nt][2] = acc[mt][nt][3] = 0.f;
                }
                r0 += __shfl_xor_sync(0xFFFFFFFFu, r0, 1);
                r0 += __shfl_xor_sync(0xFFFFFFFFu, r0, 2);
                r1 += __shfl_xor_sync(0xFFFFFFFFu, r1, 1);
                r1 += __shfl_xor_sync(0xFFFFFFFFu, r1, 2);
                ps[mt][0] += r0;
                ps[mt][1] += r1;
            }
        }

        // rotate ring: next iteration's data is in (buf+1)%3, fill target becomes old buf
        const int nbuf = (buf == 2) ? 0 : buf + 1;
        buf2 = buf;
        buf = nbuf;
    }

    if ((lane & 3) == 0) {
        #pragma unroll
        for (int mt = 0; mt < 2; ++mt) {
            red[(mw * 32 + mt * 16 + (lane >> 2)) * 2 + nw]       = ps[mt][0];
            red[(mw * 32 + mt * 16 + (lane >> 2) + 8) * 2 + nw]   = ps[mt][1];
        }
    }
    __syncthreads();
    if (tid < 128) {
        const int srow = s0 + tid;
        if (srow < SS - 1) g_scores[b * SS + srow] = red[tid * 2] + red[tid * 2 + 1];
    }
}

// ---------------------------------------------------------------------------
// Kernel B: masked log-softmax over positions -> rows 0, 3
// ---------------------------------------------------------------------------
__global__ __launch_bounds__(256) void pos_softmax_kernel(
    const int* __restrict__ lengths, const int* __restrict__ pos_action,
    float* __restrict__ out)
{
    const int b = blockIdx.x;
    const int tid = threadIdx.x;
    const int len = lengths[b] - 1;
    const float* sc = g_scores + b * SS;

    __shared__ float r1[256], r2[256];

    float m = -FLT_MAX;
    for (int s = tid; s < len; s += 256) m = fmaxf(m, sc[s]);
    r1[tid] = m; __syncthreads();
    for (int off = 128; off > 0; off >>= 1) {
        if (tid < off) r1[tid] = fmaxf(r1[tid], r1[tid + off]);
        __syncthreads();
    }
    const float mx = r1[0];
    __syncthreads();

    float s1 = 0.f, s2 = 0.f;
    for (int s = tid; s < len; s += 256) {
        float v = sc[s];
        float e = expf(v - mx);
        s1 += e; s2 += e * v;
    }
    r1[tid] = s1; r2[tid] = s2; __syncthreads();
    for (int off = 128; off > 0; off >>= 1) {
        if (tid < off) { r1[tid] += r1[tid + off]; r2[tid] += r2[tid + off]; }
        __syncthreads();
    }
    if (tid == 0) {
        float lse = mx + logf(r1[0]);
        out[0 * BN + b] = sc[pos_action[b]] - lse;
        out[3 * BN + b] = lse - r2[0] / r1[0];
    }
}

// ---------------------------------------------------------------------------
// Kernel C1: sh = relu(X @ W1s + b1s), FOUR batches per block (W1s reuse)
// grid (16, 4), 256 threads
// ---------------------------------------------------------------------------
__global__ __launch_bounds__(256) void symbol_h_kernel(
    const float* __restrict__ states, const float* __restrict__ W1s,
    const float* __restrict__ b1s, const int* __restrict__ pos_action)
{
    const int bb = blockIdx.x * 4;
    const int f = blockIdx.y * 256 + threadIdx.x;
    const int tid = threadIdx.x;

    __shared__ float xs[4][KK];
    #pragma unroll
    for (int j = 0; j < 4; ++j) {
        const float* xp = states + (size_t)(bb + j) * SS * EE + (size_t)pos_action[bb + j] * EE;
        for (int i = tid; i < KK; i += 256) xs[j][i] = xp[i];
    }
    __syncthreads();

    const float bias = b1s[f];
    float a0 = bias, a1 = bias, a2 = bias, a3 = bias;
    for (int k = 0; k < KK; ++k) {
        const float wv = W1s[(size_t)k * KK + f];
        a0 = fmaf(xs[0][k], wv, a0);
        a1 = fmaf(xs[1][k], wv, a1);
        a2 = fmaf(xs[2][k], wv, a2);
        a3 = fmaf(xs[3][k], wv, a3);
    }
    g_sh[(bb + 0) * KK + f] = fmaxf(a0, 0.f);
    g_sh[(bb + 1) * KK + f] = fmaxf(a1, 0.f);
    g_sh[(bb + 2) * KK + f] = fmaxf(a2, 0.f);
    g_sh[(bb + 3) * KK + f] = fmaxf(a3, 0.f);
}

// ---------------------------------------------------------------------------
// Kernel C2: symbol logits + softmax -> rows 1, 4
// ---------------------------------------------------------------------------
__global__ __launch_bounds__(128) void symbol_logits_kernel(
    const float* __restrict__ W2s, const float* __restrict__ b2s,
    const int* __restrict__ sym_action, float* __restrict__ out)
{
    const int b = blockIdx.x;
    const int tid = threadIdx.x;

    __shared__ float sh[KK];
    __shared__ float lg[AA];
    __shared__ float r1[128], r2[128];

    for (int i = tid; i < KK; i += 128) sh[i] = g_sh[b * KK + i];
    __syncthreads();

    float s = b2s[tid];
    for (int k = 0; k < KK; ++k) s = fmaf(sh[k], W2s[(size_t)k * AA + tid], s);
    lg[tid] = s;
    r1[tid] = s;
    __syncthreads();
    for (int off = 64; off > 0; off >>= 1) {
        if (tid < off) r1[tid] = fmaxf(r1[tid], r1[tid + off]);
        __syncthreads();
    }
    const float mx = r1[0];
    __syncthreads();
    float e = expf(lg[tid] - mx);
    r1[tid] = e; r2[tid] = e * lg[tid];
    __syncthreads();
    for (int off = 64; off > 0; off >>= 1) {
        if (tid < off) { r1[tid] += r1[tid + off]; r2[tid] += r2[tid + off]; }
        __syncthreads();
    }
    if (tid == 0) {
        float lse = mx + logf(r1[0]);
        out[1 * BN + b] = lg[sym_action[b]] - lse;
        out[4 * BN + b] = lse - r2[0] / r1[0];
    }
}

// ---------------------------------------------------------------------------
// Kernel D: value head -> row 2 (4 batches per block, Wc1 reuse)
// grid 16, 512 threads
// ---------------------------------------------------------------------------
__global__ __launch_bounds__(512) void value_kernel(
    const float* __restrict__ cls, const float* __restrict__ Wc1,
    const float* __restrict__ bc1, const float* __restrict__ wc2,
    const float* __restrict__ bc2, float* __restrict__ out)
{
    const int bb = blockIdx.x * 4;
    const int tid = threadIdx.x;

    __shared__ float xs[4][EE];
    __shared__ float red[4][512];

    #pragma unroll
    for (int j = 0; j < 4; ++j)
        if (tid < EE) xs[j][tid] = cls[(size_t)(bb + j) * EE + tid];
    __syncthreads();

    const float bias = bc1[tid];
    float a0 = bias, a1 = bias, a2 = bias, a3 = bias;
    #pragma unroll 4
    for (int k = 0; k < EE; ++k) {
        const float wv = Wc1[(size_t)k * EE + tid];
        a0 = fmaf(xs[0][k], wv, a0);
        a1 = fmaf(xs[1][k], wv, a1);
        a2 = fmaf(xs[2][k], wv, a2);
        a3 = fmaf(xs[3][k], wv, a3);
    }
    const float wc = wc2[tid];
    red[0][tid] = fmaxf(a0, 0.f) * wc;
    red[1][tid] = fmaxf(a1, 0.f) * wc;
    red[2][tid] = fmaxf(a2, 0.f) * wc;
    red[3][tid] = fmaxf(a3, 0.f) * wc;
    __syncthreads();
    for (int off = 256; off > 0; off >>= 1) {
        if (tid < off) {
            red[0][tid] += red[0][tid + off];
            red[1][tid] += red[1][tid + off];
            red[2][tid] += red[2][tid + off];
            red[3][tid] += red[3][tid + off];
        }
        __syncthreads();
    }
    if (tid < 4) out[2 * BN + bb + tid] = red[tid][0] + bc2[0];
}

// ---------------------------------------------------------------------------
extern "C" void kernel_launch(void* const* d_in, const int* in_sizes, int n_in,
                              void* d_out, int out_size)
{
    const float* states     = (const float*)d_in[0];
    const float* cls_token  = (const float*)d_in[1];
    const float* W1p        = (const float*)d_in[2];
    const float* b1p        = (const float*)d_in[3];
    const float* w2p        = (const float*)d_in[4];
    // d_in[5] = b2p : constant shift, cancels in log_softmax
    const float* W1s        = (const float*)d_in[6];
    const float* b1s        = (const float*)d_in[7];
    const float* W2s        = (const float*)d_in[8];
    const float* b2s        = (const float*)d_in[9];
    const float* Wc1        = (const float*)d_in[10];
    const float* bc1        = (const float*)d_in[11];
    const float* wc2        = (const float*)d_in[12];
    const float* bc2        = (const float*)d_in[13];
    const int*   lengths    = (const int*)d_in[14];
    const int*   pos_action = (const int*)d_in[15];
    const int*   sym_action = (const int*)d_in[16];
    float* out = (float*)d_out;

    static int configured = 0;
    if (!configured) {
        cudaFuncSetAttribute(pos_scores_mma, cudaFuncAttributeMaxDynamicSharedMemorySize, DSM_TOTAL);
        configured = 1;
    }

    conv_states_kernel<<<16384, 256>>>(states);
    conv_w1pt_kernel<<<dim3(32, 32), dim3(32, 8)>>>(W1p);
    pos_scores_mma<<<512, 256, DSM_TOTAL>>>(b1p, w2p);
    pos_softmax_kernel<<<BN, 256>>>(lengths, pos_action, out);
    symbol_h_kernel<<<dim3(16, 4), 256>>>(states, W1s, b1s, pos_action);
    symbol_logits_kernel<<<BN, 128>>>(W2s, b2s, sym_action, out);
    value_kernel<<<16, 512>>>(cls_token, Wc1, bc1, wc2, bc2, out);
}

// round 7
// speedup vs baseline: 6.5431x; 1.3695x over previous
#include <cuda_runtime.h>
#include <cuda_bf16.h>
#include <cfloat>
#include <cmath>
#include <cstdint>

#define BN 64
#define SS 1024
#define EE 512
#define KK 1024
#define AA 128

// ------------------------- device scratch -------------------------
__device__ float g_scores[BN * SS];
__device__ float g_sh[BN * KK];
__device__ __align__(128) __nv_bfloat16 g_states_h[(size_t)BN * SS * EE + 1024]; // +pad for (b=63,s=1023) tail row
__device__ __align__(128) __nv_bfloat16 g_W1pT[(size_t)KK * KK];                 // [f][k]

// ------------------------- helpers -------------------------
__device__ __forceinline__ uint32_t smem_u32(const void* p) {
    uint32_t a;
    asm("{ .reg .u64 t; cvta.to.shared.u64 t, %1; cvt.u32.u64 %0, t; }" : "=r"(a) : "l"(p));
    return a;
}
__device__ __forceinline__ void cp_async16(uint32_t dst, const void* src) {
    asm volatile("cp.async.cg.shared.global [%0], [%1], 16;" :: "r"(dst), "l"(src) : "memory");
}
#define CP_COMMIT() asm volatile("cp.async.commit_group;" ::: "memory")
#define CP_WAIT1()  asm volatile("cp.async.wait_group 1;" ::: "memory")
#define CP_WAIT0()  asm volatile("cp.async.wait_group 0;" ::: "memory")

__device__ __forceinline__ void ldmx4(uint32_t* r, uint32_t addr) {
    asm volatile("ldmatrix.sync.aligned.m8n8.x4.shared.b16 {%0,%1,%2,%3}, [%4];"
        : "=r"(r[0]), "=r"(r[1]), "=r"(r[2]), "=r"(r[3]) : "r"(addr));
}
__device__ __forceinline__ void mma16816(float* c, const uint32_t* a, uint32_t b0, uint32_t b1) {
    asm volatile("mma.sync.aligned.m16n8k16.row.col.f32.bf16.bf16.f32 "
        "{%0,%1,%2,%3}, {%4,%5,%6,%7}, {%8,%9}, {%0,%1,%2,%3};"
        : "+f"(c[0]), "+f"(c[1]), "+f"(c[2]), "+f"(c[3])
        : "r"(a[0]), "r"(a[1]), "r"(a[2]), "r"(a[3]), "r"(b0), "r"(b1));
}

// ---------------------------------------------------------------------------
// Conversion kernels
// ---------------------------------------------------------------------------
__global__ __launch_bounds__(256) void conv_states_kernel(const float* __restrict__ s) {
    size_t i = ((size_t)blockIdx.x * 256 + threadIdx.x) * 8;
    float4 v0 = *(const float4*)(s + i);
    float4 v1 = *(const float4*)(s + i + 4);
    __nv_bfloat16 h[8];
    h[0] = __float2bfloat16(v0.x); h[1] = __float2bfloat16(v0.y);
    h[2] = __float2bfloat16(v0.z); h[3] = __float2bfloat16(v0.w);
    h[4] = __float2bfloat16(v1.x); h[5] = __float2bfloat16(v1.y);
    h[6] = __float2bfloat16(v1.z); h[7] = __float2bfloat16(v1.w);
    *(uint4*)(g_states_h + i) = *(uint4*)h;
}

__global__ void conv_w1pt_kernel(const float* __restrict__ W1p) {
    __shared__ __nv_bfloat16 t[32][33];
    const int bx = blockIdx.x, by = blockIdx.y;
    const int tx = threadIdx.x, ty = threadIdx.y;   // 32 x 8
    #pragma unroll
    for (int i = 0; i < 4; ++i)
        t[ty + i * 8][tx] = __float2bfloat16(W1p[(size_t)(by * 32 + ty + i * 8) * KK + bx * 32 + tx]);
    __syncthreads();
    #pragma unroll
    for (int i = 0; i < 4; ++i)
        g_W1pT[(size_t)(bx * 32 + ty + i * 8) * KK + by * 32 + tx] = t[tx][ty + i * 8];
}

// ---------------------------------------------------------------------------
// Kernel A: scores = relu(X @ W1p + b1p) . w2p  via mma.sync bf16 (HMMA)
// grid 512 (b*8 + stile), 256 thr = 8 warps (4M x 2N), 2 CTAs/SM.
// EARLY EXIT for s-tiles entirely beyond lengths[b]-1 (masked-out positions).
// 3-stage cp.async ring, prefetch distance 2, ONE barrier per iteration.
// ---------------------------------------------------------------------------
#define TSTRIDE 72                    // halves: 144B row, 16B aligned, ldmatrix conflict-free
#define TILE_HALVES (128 * TSTRIDE)
#define TILE_BYTES  (TILE_HALVES * 2) // 18432
#define STAGE_BYTES (2 * TILE_BYTES)  // 36864 (A + B)
#define NSTAGE 3
#define RED_OFF     (NSTAGE * STAGE_BYTES) // 110592
#define DSM_TOTAL   (RED_OFF + 128 * 2 * 4)

extern __shared__ char dsm[];

__global__ __launch_bounds__(256, 2) void pos_scores_mma(
    const float* __restrict__ b1p, const float* __restrict__ w2p,
    const int* __restrict__ lengths)
{
    const int tid  = threadIdx.x;
    const int lane = tid & 31;
    const int w    = tid >> 5;
    const int mw   = w & 3;        // M warp 0..3 (32 rows each)
    const int nw   = w >> 2;       // N warp 0..1 (64 cols each)
    const int bx   = blockIdx.x;
    const int b    = bx >> 3;
    const int s0   = (bx & 7) << 7;

    // masked-out tile: scores for s >= lengths[b]-1 are never read downstream
    if (s0 >= lengths[b] - 1) return;

    const int brow0 = (b << 10) + s0;

    const uint32_t base = smem_u32(dsm);
    float* red = (float*)(dsm + RED_OFF);

    // ldmatrix per-lane address components
    const int rA = (lane & 7) + 8 * ((lane >> 3) & 1);
    const int kA = 8 * (lane >> 4);
    const int rB = (lane & 7) + 8 * (lane >> 4);
    const int kB = 8 * ((lane >> 3) & 1);

    float acc[2][8][4];
    #pragma unroll
    for (int mt = 0; mt < 2; ++mt)
        #pragma unroll
        for (int nt = 0; nt < 8; ++nt)
            #pragma unroll
            for (int r = 0; r < 4; ++r) acc[mt][nt][r] = 0.f;
    float ps[2][2] = {{0.f, 0.f}, {0.f, 0.f}};

    // stage filler: gg -> nc = gg>>4 (N chunk), k0 = (gg&15)*64; buf given explicitly
    auto fill = [&](int gg, int buf) {
        const int n0  = (gg >> 4) << 7;
        const int k0  = (gg & 15) << 6;
        const uint32_t ab = base + buf * STAGE_BYTES;
        const uint32_t bb = ab + TILE_BYTES;
        #pragma unroll
        for (int i = 0; i < 4; ++i) {
            const int c = i * 256 + tid;         // 0..1023
            const int row = c >> 3, seg = c & 7;
            const uint32_t doff = (row * TSTRIDE + seg * 8) * 2;
            cp_async16(ab + doff, g_states_h + ((size_t)(brow0 + row) << 9) + k0 + seg * 8);
            cp_async16(bb + doff, g_W1pT + ((size_t)(n0 + row) << 10) + k0 + seg * 8);
        }
    };

    fill(0, 0); CP_COMMIT();
    fill(1, 1); CP_COMMIT();

    int buf = 0;        // stage holding iteration g
    int buf2 = 2;       // stage to fill with g+2

    for (int g = 0; g < 128; ++g) {
        const int nc  = g >> 4;
        const int kit = g & 15;

        // ensure fill(g) landed (g+1 may still be in flight)
        if (g == 127) { CP_WAIT0(); } else { CP_WAIT1(); }
        __syncthreads();   // all warps past compute(g-1); buffer buf2 is reusable

        if (g + 2 < 128) { fill(g + 2, buf2); CP_COMMIT(); }

        const uint32_t ab = base + buf * STAGE_BYTES;
        const uint32_t bb = ab + TILE_BYTES;

        #pragma unroll
        for (int h = 0; h < 4; ++h) {
            uint32_t af[2][4];
            #pragma unroll
            for (int mt = 0; mt < 2; ++mt)
                ldmx4(af[mt], ab + ((mw * 32 + mt * 16 + rA) * TSTRIDE + h * 16 + kA) * 2);
            uint32_t bf[4][4];
            #pragma unroll
            for (int bt = 0; bt < 4; ++bt)
                ldmx4(bf[bt], bb + ((nw * 64 + bt * 16 + rB) * TSTRIDE + h * 16 + kB) * 2);
            #pragma unroll
            for (int mt = 0; mt < 2; ++mt)
                #pragma unroll
                for (int nt = 0; nt < 8; ++nt)
                    mma16816(acc[mt][nt], af[mt], bf[nt >> 1][(nt & 1) * 2], bf[nt >> 1][(nt & 1) * 2 + 1]);
        }

        if (kit == 15) {
            // fused epilogue for this N-chunk: relu(acc + b1p) . w2p, row-reduce
            const int nbase = nc * 128 + nw * 64 + 2 * (lane & 3);
            #pragma unroll
            for (int mt = 0; mt < 2; ++mt) {
                float r0 = 0.f, r1 = 0.f;
                #pragma unroll
                for (int nt = 0; nt < 8; ++nt) {
                    const int n = nbase + nt * 8;
                    const float bb0 = __ldg(b1p + n),     ww0 = __ldg(w2p + n);
                    const float bb1 = __ldg(b1p + n + 1), ww1 = __ldg(w2p + n + 1);
                    r0 += fmaxf(acc[mt][nt][0] + bb0, 0.f) * ww0
                        + fmaxf(acc[mt][nt][1] + bb1, 0.f) * ww1;
                    r1 += fmaxf(acc[mt][nt][2] + bb0, 0.f) * ww0
                        + fmaxf(acc[mt][nt][3] + bb1, 0.f) * ww1;
                    acc[mt][nt][0] = acc[mt][nt][1] = acc[mt][nt][2] = acc[mt][nt][3] = 0.f;
                }
                r0 += __shfl_xor_sync(0xFFFFFFFFu, r0, 1);
                r0 += __shfl_xor_sync(0xFFFFFFFFu, r0, 2);
                r1 += __shfl_xor_sync(0xFFFFFFFFu, r1, 1);
                r1 += __shfl_xor_sync(0xFFFFFFFFu, r1, 2);
                ps[mt][0] += r0;
                ps[mt][1] += r1;
            }
        }

        // rotate ring: next iteration's data is in (buf+1)%3, fill target becomes old buf
        const int nbuf = (buf == 2) ? 0 : buf + 1;
        buf2 = buf;
        buf = nbuf;
    }

    if ((lane & 3) == 0) {
        #pragma unroll
        for (int mt = 0; mt < 2; ++mt) {
            red[(mw * 32 + mt * 16 + (lane >> 2)) * 2 + nw]       = ps[mt][0];
            red[(mw * 32 + mt * 16 + (lane >> 2) + 8) * 2 + nw]   = ps[mt][1];
        }
    }
    __syncthreads();
    if (tid < 128) {
        const int srow = s0 + tid;
        if (srow < SS - 1) g_scores[b * SS + srow] = red[tid * 2] + red[tid * 2 + 1];
    }
}

// ---------------------------------------------------------------------------
// Kernel B: masked log-softmax over positions -> rows 0, 3
// ---------------------------------------------------------------------------
__global__ __launch_bounds__(256) void pos_softmax_kernel(
    const int* __restrict__ lengths, const int* __restrict__ pos_action,
    float* __restrict__ out)
{
    const int b = blockIdx.x;
    const int tid = threadIdx.x;
    const int len = lengths[b] - 1;
    const float* sc = g_scores + b * SS;

    __shared__ float r1[256], r2[256];

    float m = -FLT_MAX;
    for (int s = tid; s < len; s += 256) m = fmaxf(m, sc[s]);
    r1[tid] = m; __syncthreads();
    for (int off = 128; off > 0; off >>= 1) {
        if (tid < off) r1[tid] = fmaxf(r1[tid], r1[tid + off]);
        __syncthreads();
    }
    const float mx = r1[0];
    __syncthreads();

    float s1 = 0.f, s2 = 0.f;
    for (int s = tid; s < len; s += 256) {
        float v = sc[s];
        float e = expf(v - mx);
        s1 += e; s2 += e * v;
    }
    r1[tid] = s1; r2[tid] = s2; __syncthreads();
    for (int off = 128; off > 0; off >>= 1) {
        if (tid < off) { r1[tid] += r1[tid + off]; r2[tid] += r2[tid + off]; }
        __syncthreads();
    }
    if (tid == 0) {
        float lse = mx + logf(r1[0]);
        out[0 * BN + b] = sc[pos_action[b]] - lse;
        out[3 * BN + b] = lse - r2[0] / r1[0];
    }
}

// ---------------------------------------------------------------------------
// Kernel C1: sh = relu(X @ W1s + b1s), FOUR batches per block (W1s reuse)
// grid (16, 4), 256 threads
// ---------------------------------------------------------------------------
__global__ __launch_bounds__(256) void symbol_h_kernel(
    const float* __restrict__ states, const float* __restrict__ W1s,
    const float* __restrict__ b1s, const int* __restrict__ pos_action)
{
    const int bb = blockIdx.x * 4;
    const int f = blockIdx.y * 256 + threadIdx.x;
    const int tid = threadIdx.x;

    __shared__ float xs[4][KK];
    #pragma unroll
    for (int j = 0; j < 4; ++j) {
        const float* xp = states + (size_t)(bb + j) * SS * EE + (size_t)pos_action[bb + j] * EE;
        for (int i = tid; i < KK; i += 256) xs[j][i] = xp[i];
    }
    __syncthreads();

    const float bias = b1s[f];
    float a0 = bias, a1 = bias, a2 = bias, a3 = bias;
    for (int k = 0; k < KK; ++k) {
        const float wv = W1s[(size_t)k * KK + f];
        a0 = fmaf(xs[0][k], wv, a0);
        a1 = fmaf(xs[1][k], wv, a1);
        a2 = fmaf(xs[2][k], wv, a2);
        a3 = fmaf(xs[3][k], wv, a3);
    }
    g_sh[(bb + 0) * KK + f] = fmaxf(a0, 0.f);
    g_sh[(bb + 1) * KK + f] = fmaxf(a1, 0.f);
    g_sh[(bb + 2) * KK + f] = fmaxf(a2, 0.f);
    g_sh[(bb + 3) * KK + f] = fmaxf(a3, 0.f);
}

// ---------------------------------------------------------------------------
// Kernel C2: symbol logits + softmax -> rows 1, 4
// ---------------------------------------------------------------------------
__global__ __launch_bounds__(128) void symbol_logits_kernel(
    const float* __restrict__ W2s, const float* __restrict__ b2s,
    const int* __restrict__ sym_action, float* __restrict__ out)
{
    const int b = blockIdx.x;
    const int tid = threadIdx.x;

    __shared__ float sh[KK];
    __shared__ float lg[AA];
    __shared__ float r1[128], r2[128];

    for (int i = tid; i < KK; i += 128) sh[i] = g_sh[b * KK + i];
    __syncthreads();

    float s = b2s[tid];
    for (int k = 0; k < KK; ++k) s = fmaf(sh[k], W2s[(size_t)k * AA + tid], s);
    lg[tid] = s;
    r1[tid] = s;
    __syncthreads();
    for (int off = 64; off > 0; off >>= 1) {
        if (tid < off) r1[tid] = fmaxf(r1[tid], r1[tid + off]);
        __syncthreads();
    }
    const float mx = r1[0];
    __syncthreads();
    float e = expf(lg[tid] - mx);
    r1[tid] = e; r2[tid] = e * lg[tid];
    __syncthreads();
    for (int off = 64; off > 0; off >>= 1) {
        if (tid < off) { r1[tid] += r1[tid + off]; r2[tid] += r2[tid + off]; }
        __syncthreads();
    }
    if (tid == 0) {
        float lse = mx + logf(r1[0]);
        out[1 * BN + b] = lg[sym_action[b]] - lse;
        out[4 * BN + b] = lse - r2[0] / r1[0];
    }
}

// ---------------------------------------------------------------------------
// Kernel D: value head -> row 2 (4 batches per block, Wc1 reuse)
// grid 16, 512 threads
// ---------------------------------------------------------------------------
__global__ __launch_bounds__(512) void value_kernel(
    const float* __restrict__ cls, const float* __restrict__ Wc1,
    const float* __restrict__ bc1, const float* __restrict__ wc2,
    const float* __restrict__ bc2, float* __restrict__ out)
{
    const int bb = blockIdx.x * 4;
    const int tid = threadIdx.x;

    __shared__ float xs[4][EE];
    __shared__ float red[4][512];

    #pragma unroll
    for (int j = 0; j < 4; ++j)
        if (tid < EE) xs[j][tid] = cls[(size_t)(bb + j) * EE + tid];
    __syncthreads();

    const float bias = bc1[tid];
    float a0 = bias, a1 = bias, a2 = bias, a3 = bias;
    #pragma unroll 4
    for (int k = 0; k < EE; ++k) {
        const float wv = Wc1[(size_t)k * EE + tid];
        a0 = fmaf(xs[0][k], wv, a0);
        a1 = fmaf(xs[1][k], wv, a1);
        a2 = fmaf(xs[2][k], wv, a2);
        a3 = fmaf(xs[3][k], wv, a3);
    }
    const float wc = wc2[tid];
    red[0][tid] = fmaxf(a0, 0.f) * wc;
    red[1][tid] = fmaxf(a1, 0.f) * wc;
    red[2][tid] = fmaxf(a2, 0.f) * wc;
    red[3][tid] = fmaxf(a3, 0.f) * wc;
    __syncthreads();
    for (int off = 256; off > 0; off >>= 1) {
        if (tid < off) {
            red[0][tid] += red[0][tid + off];
            red[1][tid] += red[1][tid + off];
            red[2][tid] += red[2][tid + off];
            red[3][tid] += red[3][tid + off];
        }
        __syncthreads();
    }
    if (tid < 4) out[2 * BN + bb + tid] = red[tid][0] + bc2[0];
}

// ---------------------------------------------------------------------------
extern "C" void kernel_launch(void* const* d_in, const int* in_sizes, int n_in,
                              void* d_out, int out_size)
{
    const float* states     = (const float*)d_in[0];
    const float* cls_token  = (const float*)d_in[1];
    const float* W1p        = (const float*)d_in[2];
    const float* b1p        = (const float*)d_in[3];
    const float* w2p        = (const float*)d_in[4];
    // d_in[5] = b2p : constant shift, cancels in log_softmax
    const float* W1s        = (const float*)d_in[6];
    const float* b1s        = (const float*)d_in[7];
    const float* W2s        = (const float*)d_in[8];
    const float* b2s        = (const float*)d_in[9];
    const float* Wc1        = (const float*)d_in[10];
    const float* bc1        = (const float*)d_in[11];
    const float* wc2        = (const float*)d_in[12];
    const float* bc2        = (const float*)d_in[13];
    const int*   lengths    = (const int*)d_in[14];
    const int*   pos_action = (const int*)d_in[15];
    const int*   sym_action = (const int*)d_in[16];
    float* out = (float*)d_out;

    static int configured = 0;
    if (!configured) {
        cudaFuncSetAttribute(pos_scores_mma, cudaFuncAttributeMaxDynamicSharedMemorySize, DSM_TOTAL);
        configured = 1;
    }

    conv_states_kernel<<<16384, 256>>>(states);
    conv_w1pt_kernel<<<dim3(32, 32), dim3(32, 8)>>>(W1p);
    pos_scores_mma<<<512, 256, DSM_TOTAL>>>(b1p, w2p, lengths);
    pos_softmax_kernel<<<BN, 256>>>(lengths, pos_action, out);
    symbol_h_kernel<<<dim3(16, 4), 256>>>(states, W1s, b1s, pos_action);
    symbol_logits_kernel<<<BN, 128>>>(W2s, b2s, sym_action, out);
    value_kernel<<<16, 512>>>(cls_token, Wc1, bc1, wc2, bc2, out);
}

// round 8
// speedup vs baseline: 6.6933x; 1.0229x over previous
#include <cuda_runtime.h>
#include <cuda_bf16.h>
#include <cfloat>
#include <cmath>
#include <cstdint>

#define BN 64
#define SS 1024
#define EE 512
#define KK 1024
#define AA 128

// ------------------------- device scratch -------------------------
__device__ float g_scores[BN * SS];
__device__ float g_sh[BN * KK];
__device__ __align__(128) __nv_bfloat16 g_states_h[(size_t)BN * SS * EE + 1024]; // +pad for (b=63,s=1023) window
__device__ __align__(128) __nv_bfloat16 g_W1pT[(size_t)KK * KK];                 // [f][k]
__device__ int g_rowmap[BN * SS + 128];   // packed valid rows: value = b*1024 + s
__device__ int g_nrows;                   // number of valid rows L

// ------------------------- helpers -------------------------
__device__ __forceinline__ uint32_t smem_u32(const void* p) {
    uint32_t a;
    asm("{ .reg .u64 t; cvta.to.shared.u64 t, %1; cvt.u32.u64 %0, t; }" : "=r"(a) : "l"(p));
    return a;
}
__device__ __forceinline__ void cp_async16(uint32_t dst, const void* src) {
    asm volatile("cp.async.cg.shared.global [%0], [%1], 16;" :: "r"(dst), "l"(src) : "memory");
}
#define CP_COMMIT() asm volatile("cp.async.commit_group;" ::: "memory")
#define CP_WAIT1()  asm volatile("cp.async.wait_group 1;" ::: "memory")
#define CP_WAIT0()  asm volatile("cp.async.wait_group 0;" ::: "memory")

__device__ __forceinline__ void ldmx4(uint32_t* r, uint32_t addr) {
    asm volatile("ldmatrix.sync.aligned.m8n8.x4.shared.b16 {%0,%1,%2,%3}, [%4];"
        : "=r"(r[0]), "=r"(r[1]), "=r"(r[2]), "=r"(r[3]) : "r"(addr));
}
__device__ __forceinline__ void mma16816(float* c, const uint32_t* a, uint32_t b0, uint32_t b1) {
    asm volatile("mma.sync.aligned.m16n8k16.row.col.f32.bf16.bf16.f32 "
        "{%0,%1,%2,%3}, {%4,%5,%6,%7}, {%8,%9}, {%0,%1,%2,%3};"
        : "+f"(c[0]), "+f"(c[1]), "+f"(c[2]), "+f"(c[3])
        : "r"(a[0]), "r"(a[1]), "r"(a[2]), "r"(a[3]), "r"(b0), "r"(b1));
}

// ---------------------------------------------------------------------------
// Row map: pack all valid (b, s) with s < lengths[b]-1 into dense tile rows.
// One block, 256 threads.
// ---------------------------------------------------------------------------
__global__ __launch_bounds__(256) void build_rowmap_kernel(const int* __restrict__ lengths) {
    __shared__ int lens[64];
    __shared__ int pref[65];
    const int tid = threadIdx.x;
    if (tid < 64) lens[tid] = lengths[tid] - 1;
    __syncthreads();
    if (tid == 0) {
        int a = 0;
        pref[0] = 0;
        for (int b = 0; b < 64; ++b) { a += lens[b]; pref[b + 1] = a; }
        g_nrows = a;
    }
    __syncthreads();
    {
        const int b = tid >> 2, q = tid & 3;
        const int p = pref[b], n = lens[b], base = b << 10;
        for (int j = q; j < n; j += 4) g_rowmap[p + j] = base + j;
    }
    __syncthreads();
    if (tid == 0) {
        const int L = pref[64];
        const int Lpad = (L + 127) & ~127;
        for (int j = L; j < Lpad; ++j) g_rowmap[j] = 0;   // padded rows -> safe row 0
    }
}

// ---------------------------------------------------------------------------
// Conversion kernels
// ---------------------------------------------------------------------------
__global__ __launch_bounds__(256) void conv_states_kernel(
    const float* __restrict__ s, const int* __restrict__ lengths)
{
    size_t i = ((size_t)blockIdx.x * 256 + threadIdx.x) * 8;
    const int b  = (int)(i >> 19);             // / (SS*EE)
    const int sr = (int)((i >> 9) & 1023);     // states row within batch
    // GEMM reads bf16 rows sr and sr+1 for valid positions s < len-1  ->  need sr < len
    if (sr >= lengths[b]) return;
    float4 v0 = *(const float4*)(s + i);
    float4 v1 = *(const float4*)(s + i + 4);
    __nv_bfloat16 h[8];
    h[0] = __float2bfloat16(v0.x); h[1] = __float2bfloat16(v0.y);
    h[2] = __float2bfloat16(v0.z); h[3] = __float2bfloat16(v0.w);
    h[4] = __float2bfloat16(v1.x); h[5] = __float2bfloat16(v1.y);
    h[6] = __float2bfloat16(v1.z); h[7] = __float2bfloat16(v1.w);
    *(uint4*)(g_states_h + i) = *(uint4*)h;
}

__global__ void conv_w1pt_kernel(const float* __restrict__ W1p) {
    __shared__ __nv_bfloat16 t[32][33];
    const int bx = blockIdx.x, by = blockIdx.y;
    const int tx = threadIdx.x, ty = threadIdx.y;   // 32 x 8
    #pragma unroll
    for (int i = 0; i < 4; ++i)
        t[ty + i * 8][tx] = __float2bfloat16(W1p[(size_t)(by * 32 + ty + i * 8) * KK + bx * 32 + tx]);
    __syncthreads();
    #pragma unroll
    for (int i = 0; i < 4; ++i)
        g_W1pT[(size_t)(bx * 32 + ty + i * 8) * KK + by * 32 + tx] = t[tx][ty + i * 8];
}

// ---------------------------------------------------------------------------
// Kernel A: scores = relu(X @ W1p + b1p) . w2p  via mma.sync bf16 (HMMA)
// PACKED tiles: tile t covers rowmap[t*128 .. t*128+127] (dense valid rows).
// 256 thr = 8 warps (4M x 2N), 2 CTAs/SM, 3-stage cp.async ring, dist-2.
// ---------------------------------------------------------------------------
#define TSTRIDE 72                    // halves: 144B row, 16B aligned, ldmatrix conflict-free
#define TILE_HALVES (128 * TSTRIDE)
#define TILE_BYTES  (TILE_HALVES * 2) // 18432
#define STAGE_BYTES (2 * TILE_BYTES)  // 36864 (A + B)
#define NSTAGE 3
#define RED_OFF     (NSTAGE * STAGE_BYTES) // 110592
#define MAP_OFF     (RED_OFF + 128 * 2 * 4)
#define DSM_TOTAL   (MAP_OFF + 128 * 4)

extern __shared__ char dsm[];

__global__ __launch_bounds__(256, 2) void pos_scores_mma(
    const float* __restrict__ b1p, const float* __restrict__ w2p)
{
    const int tid  = threadIdx.x;
    const int lane = tid & 31;
    const int w    = tid >> 5;
    const int mw   = w & 3;        // M warp 0..3 (32 rows each)
    const int nw   = w >> 2;       // N warp 0..1 (64 cols each)
    const int t    = blockIdx.x;

    const int L = g_nrows;
    if (t * 128 >= L) return;

    const uint32_t base = smem_u32(dsm);
    float* red = (float*)(dsm + RED_OFF);
    int*   smap = (int*)(dsm + MAP_OFF);

    if (tid < 128) smap[tid] = g_rowmap[t * 128 + tid];
    __syncthreads();

    // ldmatrix per-lane address components
    const int rA = (lane & 7) + 8 * ((lane >> 3) & 1);
    const int kA = 8 * (lane >> 4);
    const int rB = (lane & 7) + 8 * (lane >> 4);
    const int kB = 8 * ((lane >> 3) & 1);

    float acc[2][8][4];
    #pragma unroll
    for (int mt = 0; mt < 2; ++mt)
        #pragma unroll
        for (int nt = 0; nt < 8; ++nt)
            #pragma unroll
            for (int r = 0; r < 4; ++r) acc[mt][nt][r] = 0.f;
    float ps[2][2] = {{0.f, 0.f}, {0.f, 0.f}};

    // stage filler: gg -> nc = gg>>4 (N chunk), k0 = (gg&15)*64; buf explicit
    auto fill = [&](int gg, int buf) {
        const int n0  = (gg >> 4) << 7;
        const int k0  = (gg & 15) << 6;
        const uint32_t ab = base + buf * STAGE_BYTES;
        const uint32_t bb = ab + TILE_BYTES;
        #pragma unroll
        for (int i = 0; i < 4; ++i) {
            const int c = i * 256 + tid;         // 0..1023
            const int row = c >> 3, seg = c & 7;
            const uint32_t doff = (row * TSTRIDE + seg * 8) * 2;
            const int brow = smap[row];          // packed (b<<10)+s
            cp_async16(ab + doff, g_states_h + ((size_t)brow << 9) + k0 + seg * 8);
            cp_async16(bb + doff, g_W1pT + ((size_t)(n0 + row) << 10) + k0 + seg * 8);
        }
    };

    fill(0, 0); CP_COMMIT();
    fill(1, 1); CP_COMMIT();

    int buf = 0;        // stage holding iteration g
    int buf2 = 2;       // stage to fill with g+2

    for (int g = 0; g < 128; ++g) {
        const int nc  = g >> 4;
        const int kit = g & 15;

        if (g == 127) { CP_WAIT0(); } else { CP_WAIT1(); }
        __syncthreads();   // all warps past compute(g-1); buffer buf2 reusable

        if (g + 2 < 128) { fill(g + 2, buf2); CP_COMMIT(); }

        const uint32_t ab = base + buf * STAGE_BYTES;
        const uint32_t bb = ab + TILE_BYTES;

        #pragma unroll
        for (int h = 0; h < 4; ++h) {
            uint32_t af[2][4];
            #pragma unroll
            for (int mt = 0; mt < 2; ++mt)
                ldmx4(af[mt], ab + ((mw * 32 + mt * 16 + rA) * TSTRIDE + h * 16 + kA) * 2);
            uint32_t bf[4][4];
            #pragma unroll
            for (int bt = 0; bt < 4; ++bt)
                ldmx4(bf[bt], bb + ((nw * 64 + bt * 16 + rB) * TSTRIDE + h * 16 + kB) * 2);
            #pragma unroll
            for (int mt = 0; mt < 2; ++mt)
                #pragma unroll
                for (int nt = 0; nt < 8; ++nt)
                    mma16816(acc[mt][nt], af[mt], bf[nt >> 1][(nt & 1) * 2], bf[nt >> 1][(nt & 1) * 2 + 1]);
        }

        if (kit == 15) {
            // fused epilogue for this N-chunk: relu(acc + b1p) . w2p, row-reduce
            const int nbase = nc * 128 + nw * 64 + 2 * (lane & 3);
            #pragma unroll
            for (int mt = 0; mt < 2; ++mt) {
                float r0 = 0.f, r1 = 0.f;
                #pragma unroll
                for (int nt = 0; nt < 8; ++nt) {
                    const int n = nbase + nt * 8;
                    const float bb0 = __ldg(b1p + n),     ww0 = __ldg(w2p + n);
                    const float bb1 = __ldg(b1p + n + 1), ww1 = __ldg(w2p + n + 1);
                    r0 += fmaxf(acc[mt][nt][0] + bb0, 0.f) * ww0
                        + fmaxf(acc[mt][nt][1] + bb1, 0.f) * ww1;
                    r1 += fmaxf(acc[mt][nt][2] + bb0, 0.f) * ww0
                        + fmaxf(acc[mt][nt][3] + bb1, 0.f) * ww1;
                    acc[mt][nt][0] = acc[mt][nt][1] = acc[mt][nt][2] = acc[mt][nt][3] = 0.f;
                }
                r0 += __shfl_xor_sync(0xFFFFFFFFu, r0, 1);
                r0 += __shfl_xor_sync(0xFFFFFFFFu, r0, 2);
                r1 += __shfl_xor_sync(0xFFFFFFFFu, r1, 1);
                r1 += __shfl_xor_sync(0xFFFFFFFFu, r1, 2);
                ps[mt][0] += r0;
                ps[mt][1] += r1;
            }
        }

        const int nbuf = (buf == 2) ? 0 : buf + 1;
        buf2 = buf;
        buf = nbuf;
    }

    if ((lane & 3) == 0) {
        #pragma unroll
        for (int mt = 0; mt < 2; ++mt) {
            red[(mw * 32 + mt * 16 + (lane >> 2)) * 2 + nw]       = ps[mt][0];
            red[(mw * 32 + mt * 16 + (lane >> 2) + 8) * 2 + nw]   = ps[mt][1];
        }
    }
    __syncthreads();
    if (tid < 128 && t * 128 + tid < L) {
        g_scores[smap[tid]] = red[tid * 2] + red[tid * 2 + 1];   // smap value == b*SS + s
    }
}

// ---------------------------------------------------------------------------
// Kernel B: masked log-softmax over positions -> rows 0, 3
// ---------------------------------------------------------------------------
__global__ __launch_bounds__(256) void pos_softmax_kernel(
    const int* __restrict__ lengths, const int* __restrict__ pos_action,
    float* __restrict__ out)
{
    const int b = blockIdx.x;
    const int tid = threadIdx.x;
    const int len = lengths[b] - 1;
    const float* sc = g_scores + b * SS;

    __shared__ float r1[256], r2[256];

    float m = -FLT_MAX;
    for (int s = tid; s < len; s += 256) m = fmaxf(m, sc[s]);
    r1[tid] = m; __syncthreads();
    for (int off = 128; off > 0; off >>= 1) {
        if (tid < off) r1[tid] = fmaxf(r1[tid], r1[tid + off]);
        __syncthreads();
    }
    const float mx = r1[0];
    __syncthreads();

    float s1 = 0.f, s2 = 0.f;
    for (int s = tid; s < len; s += 256) {
        float v = sc[s];
        float e = expf(v - mx);
        s1 += e; s2 += e * v;
    }
    r1[tid] = s1; r2[tid] = s2; __syncthreads();
    for (int off = 128; off > 0; off >>= 1) {
        if (tid < off) { r1[tid] += r1[tid + off]; r2[tid] += r2[tid + off]; }
        __syncthreads();
    }
    if (tid == 0) {
        float lse = mx + logf(r1[0]);
        out[0 * BN + b] = sc[pos_action[b]] - lse;
        out[3 * BN + b] = lse - r2[0] / r1[0];
    }
}

// ---------------------------------------------------------------------------
// Kernel C1: sh = relu(X @ W1s + b1s), FOUR batches per block (W1s reuse)
// grid (16, 4), 256 threads
// ---------------------------------------------------------------------------
__global__ __launch_bounds__(256) void symbol_h_kernel(
    const float* __restrict__ states, const float* __restrict__ W1s,
    const float* __restrict__ b1s, const int* __restrict__ pos_action)
{
    const int bb = blockIdx.x * 4;
    const int f = blockIdx.y * 256 + threadIdx.x;
    const int tid = threadIdx.x;

    __shared__ float xs[4][KK];
    #pragma unroll
    for (int j = 0; j < 4; ++j) {
        const float* xp = states + (size_t)(bb + j) * SS * EE + (size_t)pos_action[bb + j] * EE;
        for (int i = tid; i < KK; i += 256) xs[j][i] = xp[i];
    }
    __syncthreads();

    const float bias = b1s[f];
    float a0 = bias, a1 = bias, a2 = bias, a3 = bias;
    for (int k = 0; k < KK; ++k) {
        const float wv = W1s[(size_t)k * KK + f];
        a0 = fmaf(xs[0][k], wv, a0);
        a1 = fmaf(xs[1][k], wv, a1);
        a2 = fmaf(xs[2][k], wv, a2);
        a3 = fmaf(xs[3][k], wv, a3);
    }
    g_sh[(bb + 0) * KK + f] = fmaxf(a0, 0.f);
    g_sh[(bb + 1) * KK + f] = fmaxf(a1, 0.f);
    g_sh[(bb + 2) * KK + f] = fmaxf(a2, 0.f);
    g_sh[(bb + 3) * KK + f] = fmaxf(a3, 0.f);
}

// ---------------------------------------------------------------------------
// Kernel C2: symbol logits + softmax -> rows 1, 4
// ---------------------------------------------------------------------------
__global__ __launch_bounds__(128) void symbol_logits_kernel(
    const float* __restrict__ W2s, const float* __restrict__ b2s,
    const int* __restrict__ sym_action, float* __restrict__ out)
{
    const int b = blockIdx.x;
    const int tid = threadIdx.x;

    __shared__ float sh[KK];
    __shared__ float lg[AA];
    __shared__ float r1[128], r2[128];

    for (int i = tid; i < KK; i += 128) sh[i] = g_sh[b * KK + i];
    __syncthreads();

    float s = b2s[tid];
    for (int k = 0; k < KK; ++k) s = fmaf(sh[k], W2s[(size_t)k * AA + tid], s);
    lg[tid] = s;
    r1[tid] = s;
    __syncthreads();
    for (int off = 64; off > 0; off >>= 1) {
        if (tid < off) r1[tid] = fmaxf(r1[tid], r1[tid + off]);
        __syncthreads();
    }
    const float mx = r1[0];
    __syncthreads();
    float e = expf(lg[tid] - mx);
    r1[tid] = e; r2[tid] = e * lg[tid];
    __syncthreads();
    for (int off = 64; off > 0; off >>= 1) {
        if (tid < off) { r1[tid] += r1[tid + off]; r2[tid] += r2[tid + off]; }
        __syncthreads();
    }
    if (tid == 0) {
        float lse = mx + logf(r1[0]);
        out[1 * BN + b] = lg[sym_action[b]] - lse;
        out[4 * BN + b] = lse - r2[0] / r1[0];
    }
}

// ---------------------------------------------------------------------------
// Kernel D: value head -> row 2 (4 batches per block, Wc1 reuse)
// grid 16, 512 threads
// ---------------------------------------------------------------------------
__global__ __launch_bounds__(512) void value_kernel(
    const float* __restrict__ cls, const float* __restrict__ Wc1,
    const float* __restrict__ bc1, const float* __restrict__ wc2,
    const float* __restrict__ bc2, float* __restrict__ out)
{
    const int bb = blockIdx.x * 4;
    const int tid = threadIdx.x;

    __shared__ float xs[4][EE];
    __shared__ float red[4][512];

    #pragma unroll
    for (int j = 0; j < 4; ++j)
        if (tid < EE) xs[j][tid] = cls[(size_t)(bb + j) * EE + tid];
    __syncthreads();

    const float bias = bc1[tid];
    float a0 = bias, a1 = bias, a2 = bias, a3 = bias;
    #pragma unroll 4
    for (int k = 0; k < EE; ++k) {
        const float wv = Wc1[(size_t)k * EE + tid];
        a0 = fmaf(xs[0][k], wv, a0);
        a1 = fmaf(xs[1][k], wv, a1);
        a2 = fmaf(xs[2][k], wv, a2);
        a3 = fmaf(xs[3][k], wv, a3);
    }
    const float wc = wc2[tid];
    red[0][tid] = fmaxf(a0, 0.f) * wc;
    red[1][tid] = fmaxf(a1, 0.f) * wc;
    red[2][tid] = fmaxf(a2, 0.f) * wc;
    red[3][tid] = fmaxf(a3, 0.f) * wc;
    __syncthreads();
    for (int off = 256; off > 0; off >>= 1) {
        if (tid < off) {
            red[0][tid] += red[0][tid + off];
            red[1][tid] += red[1][tid + off];
            red[2][tid] += red[2][tid + off];
            red[3][tid] += red[3][tid + off];
        }
        __syncthreads();
    }
    if (tid < 4) out[2 * BN + bb + tid] = red[tid][0] + bc2[0];
}

// ---------------------------------------------------------------------------
extern "C" void kernel_launch(void* const* d_in, const int* in_sizes, int n_in,
                              void* d_out, int out_size)
{
    const float* states     = (const float*)d_in[0];
    const float* cls_token  = (const float*)d_in[1];
    const float* W1p        = (const float*)d_in[2];
    const float* b1p        = (const float*)d_in[3];
    const float* w2p        = (const float*)d_in[4];
    // d_in[5] = b2p : constant shift, cancels in log_softmax
    const float* W1s        = (const float*)d_in[6];
    const float* b1s        = (const float*)d_in[7];
    const float* W2s        = (const float*)d_in[8];
    const float* b2s        = (const float*)d_in[9];
    const float* Wc1        = (const float*)d_in[10];
    const float* bc1        = (const float*)d_in[11];
    const float* wc2        = (const float*)d_in[12];
    const float* bc2        = (const float*)d_in[13];
    const int*   lengths    = (const int*)d_in[14];
    const int*   pos_action = (const int*)d_in[15];
    const int*   sym_action = (const int*)d_in[16];
    float* out = (float*)d_out;

    static int configured = 0;
    if (!configured) {
        cudaFuncSetAttribute(pos_scores_mma, cudaFuncAttributeMaxDynamicSharedMemorySize, DSM_TOTAL);
        configured = 1;
    }

    build_rowmap_kernel<<<1, 256>>>(lengths);
    conv_states_kernel<<<16384, 256>>>(states, lengths);
    conv_w1pt_kernel<<<dim3(32, 32), dim3(32, 8)>>>(W1p);
    pos_scores_mma<<<512, 256, DSM_TOTAL>>>(b1p, w2p);
    pos_softmax_kernel<<<BN, 256>>>(lengths, pos_action, out);
    symbol_h_kernel<<<dim3(16, 4), 256>>>(states, W1s, b1s, pos_action);
    symbol_logits_kernel<<<BN, 128>>>(W2s, b2s, sym_action, out);
    value_kernel<<<16, 512>>>(cls_token, Wc1, bc1, wc2, bc2, out);
}

// round 9
// speedup vs baseline: 8.3621x; 1.2493x over previous
#include <cuda_runtime.h>
#include <cuda_bf16.h>
#include <cfloat>
#include <cmath>
#include <cstdint>

#define BN 64
#define SS 1024
#define EE 512
#define KK 1024
#define AA 128

// ------------------------- device scratch -------------------------
__device__ float g_scores[BN * SS];
__device__ float g_sh[BN * KK];
__device__ __align__(128) __nv_bfloat16 g_states_h[(size_t)BN * SS * EE + 1024]; // +pad for (b=63,s=1023) window
__device__ __align__(128) __nv_bfloat16 g_W1pT[(size_t)KK * KK];                 // [f][k]
__device__ int g_rowmap[BN * SS + 128];   // packed valid rows: value = b*1024 + s
__device__ int g_nrows;                   // number of valid rows L

// ------------------------- helpers -------------------------
__device__ __forceinline__ uint32_t smem_u32(const void* p) {
    uint32_t a;
    asm("{ .reg .u64 t; cvta.to.shared.u64 t, %1; cvt.u32.u64 %0, t; }" : "=r"(a) : "l"(p));
    return a;
}
__device__ __forceinline__ void cp_async16(uint32_t dst, const void* src) {
    asm volatile("cp.async.cg.shared.global [%0], [%1], 16;" :: "r"(dst), "l"(src) : "memory");
}
#define CP_COMMIT() asm volatile("cp.async.commit_group;" ::: "memory")
#define CP_WAIT1()  asm volatile("cp.async.wait_group 1;" ::: "memory")
#define CP_WAIT0()  asm volatile("cp.async.wait_group 0;" ::: "memory")

__device__ __forceinline__ void ldmx4(uint32_t* r, uint32_t addr) {
    asm volatile("ldmatrix.sync.aligned.m8n8.x4.shared.b16 {%0,%1,%2,%3}, [%4];"
        : "=r"(r[0]), "=r"(r[1]), "=r"(r[2]), "=r"(r[3]) : "r"(addr));
}
__device__ __forceinline__ void mma16816(float* c, const uint32_t* a, uint32_t b0, uint32_t b1) {
    asm volatile("mma.sync.aligned.m16n8k16.row.col.f32.bf16.bf16.f32 "
        "{%0,%1,%2,%3}, {%4,%5,%6,%7}, {%8,%9}, {%0,%1,%2,%3};"
        : "+f"(c[0]), "+f"(c[1]), "+f"(c[2]), "+f"(c[3])
        : "r"(a[0]), "r"(a[1]), "r"(a[2]), "r"(a[3]), "r"(b0), "r"(b1));
}

// ---------------------------------------------------------------------------
// Row map: pack all valid (b, s) with s < lengths[b]-1 into dense tile rows.
// grid 64 (one block per batch), 256 threads.
// ---------------------------------------------------------------------------
__global__ __launch_bounds__(256) void build_rowmap_kernel(const int* __restrict__ lengths) {
    __shared__ int pref[65];
    const int b = blockIdx.x;
    const int tid = threadIdx.x;
    if (tid == 0) {
        int a = 0; pref[0] = 0;
        for (int i = 0; i < 64; ++i) { a += lengths[i] - 1; pref[i + 1] = a; }
        if (b == 0) g_nrows = a;
    }
    __syncthreads();
    const int p = pref[b], n = pref[b + 1] - p, base = b << 10;
    for (int j = tid; j < n; j += 256) g_rowmap[p + j] = base + j;
    if (b == 63) {
        const int L = pref[64];
        const int Lpad = (L + 127) & ~127;
        for (int j = L + tid; j < Lpad; j += 256) g_rowmap[j] = 0;  // padded rows -> safe row 0
    }
}

// ---------------------------------------------------------------------------
// Conversion kernels
// ---------------------------------------------------------------------------
__global__ __launch_bounds__(256) void conv_states_kernel(
    const float* __restrict__ s, const int* __restrict__ lengths)
{
    size_t i = ((size_t)blockIdx.x * 256 + threadIdx.x) * 8;
    const int b  = (int)(i >> 19);             // / (SS*EE)
    const int sr = (int)((i >> 9) & 1023);     // states row within batch
    if (sr >= lengths[b]) return;              // GEMM never reads beyond row len-1 (+1 window)
    float4 v0 = *(const float4*)(s + i);
    float4 v1 = *(const float4*)(s + i + 4);
    __nv_bfloat16 h[8];
    h[0] = __float2bfloat16(v0.x); h[1] = __float2bfloat16(v0.y);
    h[2] = __float2bfloat16(v0.z); h[3] = __float2bfloat16(v0.w);
    h[4] = __float2bfloat16(v1.x); h[5] = __float2bfloat16(v1.y);
    h[6] = __float2bfloat16(v1.z); h[7] = __float2bfloat16(v1.w);
    *(uint4*)(g_states_h + i) = *(uint4*)h;
}

__global__ void conv_w1pt_kernel(const float* __restrict__ W1p) {
    __shared__ __nv_bfloat16 t[32][33];
    const int bx = blockIdx.x, by = blockIdx.y;
    const int tx = threadIdx.x, ty = threadIdx.y;   // 32 x 8
    #pragma unroll
    for (int i = 0; i < 4; ++i)
        t[ty + i * 8][tx] = __float2bfloat16(W1p[(size_t)(by * 32 + ty + i * 8) * KK + bx * 32 + tx]);
    __syncthreads();
    #pragma unroll
    for (int i = 0; i < 4; ++i)
        g_W1pT[(size_t)(bx * 32 + ty + i * 8) * KK + by * 32 + tx] = t[tx][ty + i * 8];
}

// ---------------------------------------------------------------------------
// Kernel A: scores = relu(X @ W1p + b1p) . w2p  via mma.sync bf16 (HMMA)
// PACKED tiles: tile t covers rowmap[t*128 .. t*128+127] (dense valid rows).
// 256 thr = 8 warps (4M x 2N), 2 CTAs/SM, 3-stage cp.async ring, dist-2.
// ---------------------------------------------------------------------------
#define TSTRIDE 72                    // halves: 144B row, 16B aligned, ldmatrix conflict-free
#define TILE_HALVES (128 * TSTRIDE)
#define TILE_BYTES  (TILE_HALVES * 2) // 18432
#define STAGE_BYTES (2 * TILE_BYTES)  // 36864 (A + B)
#define NSTAGE 3
#define RED_OFF     (NSTAGE * STAGE_BYTES) // 110592
#define MAP_OFF     (RED_OFF + 128 * 2 * 4)
#define DSM_TOTAL   (MAP_OFF + 128 * 4)

extern __shared__ char dsm[];

__global__ __launch_bounds__(256, 2) void pos_scores_mma(
    const float* __restrict__ b1p, const float* __restrict__ w2p)
{
    const int tid  = threadIdx.x;
    const int lane = tid & 31;
    const int w    = tid >> 5;
    const int mw   = w & 3;        // M warp 0..3 (32 rows each)
    const int nw   = w >> 2;       // N warp 0..1 (64 cols each)
    const int t    = blockIdx.x;

    const int L = g_nrows;
    if (t * 128 >= L) return;

    const uint32_t base = smem_u32(dsm);
    float* red = (float*)(dsm + RED_OFF);
    int*   smap = (int*)(dsm + MAP_OFF);

    if (tid < 128) smap[tid] = g_rowmap[t * 128 + tid];
    __syncthreads();

    // ldmatrix per-lane address components
    const int rA = (lane & 7) + 8 * ((lane >> 3) & 1);
    const int kA = 8 * (lane >> 4);
    const int rB = (lane & 7) + 8 * (lane >> 4);
    const int kB = 8 * ((lane >> 3) & 1);

    float acc[2][8][4];
    #pragma unroll
    for (int mt = 0; mt < 2; ++mt)
        #pragma unroll
        for (int nt = 0; nt < 8; ++nt)
            #pragma unroll
            for (int r = 0; r < 4; ++r) acc[mt][nt][r] = 0.f;
    float ps[2][2] = {{0.f, 0.f}, {0.f, 0.f}};

    // stage filler: gg -> nc = gg>>4 (N chunk), k0 = (gg&15)*64; buf explicit
    auto fill = [&](int gg, int buf) {
        const int n0  = (gg >> 4) << 7;
        const int k0  = (gg & 15) << 6;
        const uint32_t ab = base + buf * STAGE_BYTES;
        const uint32_t bb = ab + TILE_BYTES;
        #pragma unroll
        for (int i = 0; i < 4; ++i) {
            const int c = i * 256 + tid;         // 0..1023
            const int row = c >> 3, seg = c & 7;
            const uint32_t doff = (row * TSTRIDE + seg * 8) * 2;
            const int brow = smap[row];          // packed (b<<10)+s
            cp_async16(ab + doff, g_states_h + ((size_t)brow << 9) + k0 + seg * 8);
            cp_async16(bb + doff, g_W1pT + ((size_t)(n0 + row) << 10) + k0 + seg * 8);
        }
    };

    fill(0, 0); CP_COMMIT();
    fill(1, 1); CP_COMMIT();

    int buf = 0;        // stage holding iteration g
    int buf2 = 2;       // stage to fill with g+2

    for (int g = 0; g < 128; ++g) {
        const int nc  = g >> 4;
        const int kit = g & 15;

        if (g == 127) { CP_WAIT0(); } else { CP_WAIT1(); }
        __syncthreads();   // all warps past compute(g-1); buffer buf2 reusable

        if (g + 2 < 128) { fill(g + 2, buf2); CP_COMMIT(); }

        const uint32_t ab = base + buf * STAGE_BYTES;
        const uint32_t bb = ab + TILE_BYTES;

        #pragma unroll
        for (int h = 0; h < 4; ++h) {
            uint32_t af[2][4];
            #pragma unroll
            for (int mt = 0; mt < 2; ++mt)
                ldmx4(af[mt], ab + ((mw * 32 + mt * 16 + rA) * TSTRIDE + h * 16 + kA) * 2);
            uint32_t bf[4][4];
            #pragma unroll
            for (int bt = 0; bt < 4; ++bt)
                ldmx4(bf[bt], bb + ((nw * 64 + bt * 16 + rB) * TSTRIDE + h * 16 + kB) * 2);
            #pragma unroll
            for (int mt = 0; mt < 2; ++mt)
                #pragma unroll
                for (int nt = 0; nt < 8; ++nt)
                    mma16816(acc[mt][nt], af[mt], bf[nt >> 1][(nt & 1) * 2], bf[nt >> 1][(nt & 1) * 2 + 1]);
        }

        if (kit == 15) {
            // fused epilogue for this N-chunk: relu(acc + b1p) . w2p, row-reduce
            const int nbase = nc * 128 + nw * 64 + 2 * (lane & 3);
            #pragma unroll
            for (int mt = 0; mt < 2; ++mt) {
                float r0 = 0.f, r1 = 0.f;
                #pragma unroll
                for (int nt = 0; nt < 8; ++nt) {
                    const int n = nbase + nt * 8;
                    const float bb0 = __ldg(b1p + n),     ww0 = __ldg(w2p + n);
                    const float bb1 = __ldg(b1p + n + 1), ww1 = __ldg(w2p + n + 1);
                    r0 += fmaxf(acc[mt][nt][0] + bb0, 0.f) * ww0
                        + fmaxf(acc[mt][nt][1] + bb1, 0.f) * ww1;
                    r1 += fmaxf(acc[mt][nt][2] + bb0, 0.f) * ww0
                        + fmaxf(acc[mt][nt][3] + bb1, 0.f) * ww1;
                    acc[mt][nt][0] = acc[mt][nt][1] = acc[mt][nt][2] = acc[mt][nt][3] = 0.f;
                }
                r0 += __shfl_xor_sync(0xFFFFFFFFu, r0, 1);
                r0 += __shfl_xor_sync(0xFFFFFFFFu, r0, 2);
                r1 += __shfl_xor_sync(0xFFFFFFFFu, r1, 1);
                r1 += __shfl_xor_sync(0xFFFFFFFFu, r1, 2);
                ps[mt][0] += r0;
                ps[mt][1] += r1;
            }
        }

        const int nbuf = (buf == 2) ? 0 : buf + 1;
        buf2 = buf;
        buf = nbuf;
    }

    if ((lane & 3) == 0) {
        #pragma unroll
        for (int mt = 0; mt < 2; ++mt) {
            red[(mw * 32 + mt * 16 + (lane >> 2)) * 2 + nw]       = ps[mt][0];
            red[(mw * 32 + mt * 16 + (lane >> 2) + 8) * 2 + nw]   = ps[mt][1];
        }
    }
    __syncthreads();
    if (tid < 128 && t * 128 + tid < L) {
        g_scores[smap[tid]] = red[tid * 2] + red[tid * 2 + 1];   // smap value == b*SS + s
    }
}

// ---------------------------------------------------------------------------
// Kernel B: masked log-softmax over positions -> rows 0, 3
// ---------------------------------------------------------------------------
__global__ __launch_bounds__(256) void pos_softmax_kernel(
    const int* __restrict__ lengths, const int* __restrict__ pos_action,
    float* __restrict__ out)
{
    const int b = blockIdx.x;
    const int tid = threadIdx.x;
    const int len = lengths[b] - 1;
    const float* sc = g_scores + b * SS;

    __shared__ float r1[256], r2[256];

    float m = -FLT_MAX;
    for (int s = tid; s < len; s += 256) m = fmaxf(m, sc[s]);
    r1[tid] = m; __syncthreads();
    for (int off = 128; off > 0; off >>= 1) {
        if (tid < off) r1[tid] = fmaxf(r1[tid], r1[tid + off]);
        __syncthreads();
    }
    const float mx = r1[0];
    __syncthreads();

    float s1 = 0.f, s2 = 0.f;
    for (int s = tid; s < len; s += 256) {
        float v = sc[s];
        float e = expf(v - mx);
        s1 += e; s2 += e * v;
    }
    r1[tid] = s1; r2[tid] = s2; __syncthreads();
    for (int off = 128; off > 0; off >>= 1) {
        if (tid < off) { r1[tid] += r1[tid + off]; r2[tid] += r2[tid + off]; }
        __syncthreads();
    }
    if (tid == 0) {
        float lse = mx + logf(r1[0]);
        out[0 * BN + b] = sc[pos_action[b]] - lse;
        out[3 * BN + b] = lse - r2[0] / r1[0];
    }
}

// ---------------------------------------------------------------------------
// Kernel C1: sh = relu(X @ W1s + b1s). grid (64, 4): block (batch, f-chunk 256).
// 1 f per thread, unroll-16 k loop (independent loads hide L2 latency).
// ---------------------------------------------------------------------------
__global__ __launch_bounds__(256) void symbol_h_kernel(
    const float* __restrict__ states, const float* __restrict__ W1s,
    const float* __restrict__ b1s, const int* __restrict__ pos_action)
{
    const int b = blockIdx.x;
    const int f = blockIdx.y * 256 + threadIdx.x;
    const int tid = threadIdx.x;

    __shared__ float xs[KK];
    const float* xp = states + (size_t)b * SS * EE + (size_t)pos_action[b] * EE;
    for (int i = tid; i < KK; i += 256) xs[i] = xp[i];
    __syncthreads();

    float a = b1s[f];
    #pragma unroll 16
    for (int k = 0; k < KK; ++k)
        a = fmaf(xs[k], W1s[(size_t)k * KK + f], a);
    g_sh[b * KK + f] = fmaxf(a, 0.f);
}

// ---------------------------------------------------------------------------
// Kernel C2: symbol logits + softmax -> rows 1, 4
// ---------------------------------------------------------------------------
__global__ __launch_bounds__(128) void symbol_logits_kernel(
    const float* __restrict__ W2s, const float* __restrict__ b2s,
    const int* __restrict__ sym_action, float* __restrict__ out)
{
    const int b = blockIdx.x;
    const int tid = threadIdx.x;

    __shared__ float sh[KK];
    __shared__ float lg[AA];
    __shared__ float r1[128], r2[128];

    for (int i = tid; i < KK; i += 128) sh[i] = g_sh[b * KK + i];
    __syncthreads();

    float s = b2s[tid];
    #pragma unroll 8
    for (int k = 0; k < KK; ++k) s = fmaf(sh[k], W2s[(size_t)k * AA + tid], s);
    lg[tid] = s;
    r1[tid] = s;
    __syncthreads();
    for (int off = 64; off > 0; off >>= 1) {
        if (tid < off) r1[tid] = fmaxf(r1[tid], r1[tid + off]);
        __syncthreads();
    }
    const float mx = r1[0];
    __syncthreads();
    float e = expf(lg[tid] - mx);
    r1[tid] = e; r2[tid] = e * lg[tid];
    __syncthreads();
    for (int off = 64; off > 0; off >>= 1) {
        if (tid < off) { r1[tid] += r1[tid + off]; r2[tid] += r2[tid + off]; }
        __syncthreads();
    }
    if (tid == 0) {
        float lse = mx + logf(r1[0]);
        out[1 * BN + b] = lg[sym_action[b]] - lse;
        out[4 * BN + b] = lse - r2[0] / r1[0];
    }
}

// ---------------------------------------------------------------------------
// Kernel D: value head -> row 2. grid 64 (1 batch/block), 256 threads, 2 f each.
// ---------------------------------------------------------------------------
__global__ __launch_bounds__(256) void value_kernel(
    const float* __restrict__ cls, const float* __restrict__ Wc1,
    const float* __restrict__ bc1, const float* __restrict__ wc2,
    const float* __restrict__ bc2, float* __restrict__ out)
{
    const int b = blockIdx.x;
    const int tid = threadIdx.x;

    __shared__ float xs[EE];
    __shared__ float r1[256];

    for (int i = tid; i < EE; i += 256) xs[i] = cls[(size_t)b * EE + i];
    __syncthreads();

    float a0 = bc1[tid], a1 = bc1[tid + 256];
    #pragma unroll 8
    for (int k = 0; k < EE; ++k) {
        const float xk = xs[k];
        const float* wr = Wc1 + (size_t)k * EE;
        a0 = fmaf(xk, wr[tid],       a0);
        a1 = fmaf(xk, wr[tid + 256], a1);
    }
    r1[tid] = fmaxf(a0, 0.f) * wc2[tid] + fmaxf(a1, 0.f) * wc2[tid + 256];
    __syncthreads();
    for (int off = 128; off > 0; off >>= 1) {
        if (tid < off) r1[tid] += r1[tid + off];
        __syncthreads();
    }
    if (tid == 0) out[2 * BN + b] = r1[0] + bc2[0];
}

// ---------------------------------------------------------------------------
extern "C" void kernel_launch(void* const* d_in, const int* in_sizes, int n_in,
                              void* d_out, int out_size)
{
    const float* states     = (const float*)d_in[0];
    const float* cls_token  = (const float*)d_in[1];
    const float* W1p        = (const float*)d_in[2];
    const float* b1p        = (const float*)d_in[3];
    const float* w2p        = (const float*)d_in[4];
    // d_in[5] = b2p : constant shift, cancels in log_softmax
    const float* W1s        = (const float*)d_in[6];
    const float* b1s        = (const float*)d_in[7];
    const float* W2s        = (const float*)d_in[8];
    const float* b2s        = (const float*)d_in[9];
    const float* Wc1        = (const float*)d_in[10];
    const float* bc1        = (const float*)d_in[11];
    const float* wc2        = (const float*)d_in[12];
    const float* bc2        = (const float*)d_in[13];
    const int*   lengths    = (const int*)d_in[14];
    const int*   pos_action = (const int*)d_in[15];
    const int*   sym_action = (const int*)d_in[16];
    float* out = (float*)d_out;

    static int configured = 0;
    static cudaStream_t s1, s2;
    static cudaEvent_t efork, ejoin1, ejoin2;
    if (!configured) {
        cudaFuncSetAttribute(pos_scores_mma, cudaFuncAttributeMaxDynamicSharedMemorySize, DSM_TOTAL);
        cudaStreamCreateWithFlags(&s1, cudaStreamNonBlocking);
        cudaStreamCreateWithFlags(&s2, cudaStreamNonBlocking);
        cudaEventCreateWithFlags(&efork,  cudaEventDisableTiming);
        cudaEventCreateWithFlags(&ejoin1, cudaEventDisableTiming);
        cudaEventCreateWithFlags(&ejoin2, cudaEventDisableTiming);
        configured = 1;
    }

    // fork: side branches depend only on kernel inputs
    cudaEventRecord(efork, 0);
    cudaStreamWaitEvent(s1, efork, 0);
    cudaStreamWaitEvent(s2, efork, 0);

    // branch s1: symbol head (independent of GEMM chain)
    symbol_h_kernel<<<dim3(64, 4), 256, 0, s1>>>(states, W1s, b1s, pos_action);
    symbol_logits_kernel<<<BN, 128, 0, s1>>>(W2s, b2s, sym_action, out);
    cudaEventRecord(ejoin1, s1);

    // branch s2: value head
    value_kernel<<<BN, 256, 0, s2>>>(cls_token, Wc1, bc1, wc2, bc2, out);
    cudaEventRecord(ejoin2, s2);

    // main branch: position head chain
    build_rowmap_kernel<<<BN, 256>>>(lengths);
    conv_states_kernel<<<16384, 256>>>(states, lengths);
    conv_w1pt_kernel<<<dim3(32, 32), dim3(32, 8)>>>(W1p);
    pos_scores_mma<<<512, 256, DSM_TOTAL>>>(b1p, w2p);
    pos_softmax_kernel<<<BN, 256>>>(lengths, pos_action, out);

    // join
    cudaStreamWaitEvent(0, ejoin1, 0);
    cudaStreamWaitEvent(0, ejoin2, 0);
}